// round 13
// baseline (speedup 1.0000x reference)
#include <cuda_runtime.h>
#include <cuda_bf16.h>
#include <math.h>
#include <stdint.h>

#define BB 4
#define SS 2048
#define DMM 1024
#define NTOK (BB*SS)          /* 8192 */
#define CHL 64
#define NCH (NTOK/CHL)        /* 128 */

// ---------------- scratch ----------------
__device__ float g_Wcat[256*DMM];
__device__ float g_bcat[256];
__device__ float g_v[NTOK*64];
__device__ __nv_bfloat16 g_qh[NTOK*64], g_ql[NTOK*64];
__device__ __nv_bfloat16 g_kh[NTOK*64], g_kl[NTOK*64];
__device__ __nv_bfloat16 g_ah[NTOK*64], g_al[NTOK*64];
__device__ __nv_bfloat16 g_MTh[16384*64], g_MTl[16384*64];   // [(c*128+d)][j]
__device__ __nv_bfloat16 g_Wd2h[8192*64], g_Wd2l[8192*64];   // [(c*64+v)][j]
__device__ __nv_bfloat16 g_Wu3h[8192*64], g_Wu3l[8192*64];   // [(v*128+c)][k]
__device__ float g_bin[NTOK*128];
__device__ __nv_bfloat16 g_Ah[(size_t)NTOK*16384];           // 256 MB [t][c*128+d] hi
__device__ __nv_bfloat16 g_Al[(size_t)NTOK*16384];           // 256 MB lo
__device__ float g_P[(size_t)NCH*16384];                     // Q layout: [chunk][n*128+r] = P^T
__device__ float g_d[NCH*128];
__device__ float g_cb[NCH*128];
__device__ float g_c[NTOK*128];

// ---------------- f32x2 helpers ----------------
__device__ __forceinline__ unsigned long long dupf(float a) {
    unsigned long long r;
    asm("mov.b64 %0, {%1, %1};" : "=l"(r) : "f"(a));
    return r;
}
__device__ __forceinline__ void fma2(unsigned long long& c, unsigned long long a, unsigned long long b) {
    asm("fma.rn.f32x2 %0, %1, %2, %0;" : "+l"(c) : "l"(a), "l"(b));
}
__device__ __forceinline__ void unpk(unsigned long long v, float& lo, float& hi) {
    asm("mov.b64 {%0, %1}, %2;" : "=f"(lo), "=f"(hi) : "l"(v));
}

// ---------------- mma helpers ----------------
__device__ __forceinline__ uint32_t smem_u32(const void* p) {
    uint32_t a;
    asm("{ .reg .u64 t; cvta.to.shared.u64 t, %1; cvt.u32.u64 %0, t; }" : "=r"(a) : "l"(p));
    return a;
}
#define LDSM4(r, addr) \
    asm volatile("ldmatrix.sync.aligned.m8n8.x4.shared.b16 {%0,%1,%2,%3}, [%4];" \
        : "=r"((r)[0]), "=r"((r)[1]), "=r"((r)[2]), "=r"((r)[3]) : "r"(addr))
#define MMA16816(d, a, b0, b1) \
    asm volatile("mma.sync.aligned.m16n8k16.row.col.f32.bf16.bf16.f32 " \
        "{%0,%1,%2,%3}, {%4,%5,%6,%7}, {%8,%9}, {%0,%1,%2,%3};" \
        : "+f"((d)[0]), "+f"((d)[1]), "+f"((d)[2]), "+f"((d)[3]) \
        : "r"((a)[0]), "r"((a)[1]), "r"((a)[2]), "r"((a)[3]), "r"(b0), "r"(b1))
#define CP16(dst, src) \
    asm volatile("cp.async.cg.shared.global [%0], [%1], 16;" :: "r"(dst), "l"(src) : "memory")
#define CP_COMMIT() asm volatile("cp.async.commit_group;" ::: "memory")
#define CP_WAIT0()  asm volatile("cp.async.wait_all;" ::: "memory")

__device__ __forceinline__ void split_bf16(float x, __nv_bfloat16& h, __nv_bfloat16& l) {
    h = __float2bfloat16(x);
    l = __float2bfloat16(x - __bfloat162float(h));
}

// ---------------- merged prep (unchanged) ----------------
__global__ __launch_bounds__(256) void prep_all(
        const float* __restrict__ Wq, const float* __restrict__ bq,
        const float* __restrict__ Wk, const float* __restrict__ bk,
        const float* __restrict__ Wv, const float* __restrict__ bv,
        const float* __restrict__ Wa, const float* __restrict__ ba,
        const float* __restrict__ Wd, const float* __restrict__ Wu) {
    __shared__ float sd[128][33];
    __shared__ float su[32][128];
    int bid = blockIdx.x;
    int tid = threadIdx.x;
    if (bid < 64) {
        int j = bid;
        int c0 = tid >> 1;
        int dbase = (tid & 1) * 64;
        float acc[64];
        #pragma unroll
        for (int i = 0; i < 64; i++) acc[i] = 0.f;
        for (int vp = 0; vp < 2; vp++) {
            for (int l = tid; l < 128*32; l += 256) {
                int c = l >> 5, v = l & 31;
                sd[c][v] = Wd[(size_t)c*4096 + j*64 + vp*32 + v];
            }
            for (int l = tid; l < 32*128; l += 256) {
                int v = l >> 7, d = l & 127;
                su[v][d] = Wu[(size_t)(j*64 + vp*32 + v)*128 + d];
            }
            __syncthreads();
            #pragma unroll 8
            for (int v = 0; v < 32; v++) {
                float a = sd[c0][v];
                #pragma unroll
                for (int d = 0; d < 64; d++)
                    acc[d] += a * su[v][dbase + d];
            }
            __syncthreads();
        }
        for (int d = 0; d < 64; d++) {
            __nv_bfloat16 h, l;
            split_bf16(acc[d], h, l);
            size_t pos = (size_t)(c0*128 + dbase + d)*64 + j;
            g_MTh[pos] = h; g_MTl[pos] = l;
        }
    } else if (bid < 1088) {
        int idx = (bid - 64)*256 + tid;
        int r = idx >> 10, cc = idx & 1023;
        float w;
        if (r < 64)       w = Wq[r*DMM + cc];
        else if (r < 128) w = Wk[(r-64)*DMM + cc];
        else if (r < 192) w = Wv[(r-128)*DMM + cc];
        else              w = Wa[(r-192)*DMM + cc];
        g_Wcat[idx] = w;
        if (bid == 64) {
            g_bcat[tid] = (tid < 64) ? bq[tid] :
                          (tid < 128) ? bk[tid-64] :
                          (tid < 192) ? bv[tid-128] : ba[tid-192];
        }
    } else if (bid < 3136) {
        int idx = (bid - 1088)*256 + tid;       // over 128*4096
        int c = idx >> 12, rest = idx & 4095;
        int j = rest >> 6, v = rest & 63;
        __nv_bfloat16 h, l;
        split_bf16(Wd[idx], h, l);
        size_t pos = (size_t)((c<<6) + v)*64 + j;
        g_Wd2h[pos] = h; g_Wd2l[pos] = l;
    } else {
        int idx = (bid - 3136)*256 + tid;       // over 4096*128
        int kv = idx >> 7, c = idx & 127;
        int k = kv >> 6, v = kv & 63;
        __nv_bfloat16 h, l;
        split_bf16(Wu[idx], h, l);
        size_t pos = (size_t)(v*128 + c)*64 + k;
        g_Wu3h[pos] = h; g_Wu3l[pos] = l;
    }
}

// ---------------- projection GEMM (unchanged) ----------------
__global__ void __launch_bounds__(256) gemm_proj(const float* __restrict__ A,
                                                 const float* __restrict__ B,
                                                 int M, int N, int K) {
    __shared__ __align__(16) float As[2][16][132];
    __shared__ __align__(16) float Bs[2][16][132];
    int tid = threadIdx.x;
    int tx = tid & 15, ty = tid >> 4;
    int row0 = blockIdx.y*128, col0 = blockIdx.x*128;
    int lr = tid >> 1;
    int lk = (tid & 1) * 8;
    const float* Ap = A + (size_t)(row0+lr)*K + lk;
    const float* Bp = B + (size_t)(col0+lr)*K + lk;

    unsigned long long acc[8][4];
    #pragma unroll
    for (int i = 0; i < 8; i++)
        #pragma unroll
        for (int j = 0; j < 4; j++) acc[i][j] = 0ULL;

    int nt = K >> 4;
    {
        float4 a0 = *(const float4*)(Ap + 0);
        float4 a1 = *(const float4*)(Ap + 4);
        float4 b0 = *(const float4*)(Bp + 0);
        float4 b1 = *(const float4*)(Bp + 4);
        As[0][lk+0][lr]=a0.x; As[0][lk+1][lr]=a0.y; As[0][lk+2][lr]=a0.z; As[0][lk+3][lr]=a0.w;
        As[0][lk+4][lr]=a1.x; As[0][lk+5][lr]=a1.y; As[0][lk+6][lr]=a1.z; As[0][lk+7][lr]=a1.w;
        Bs[0][lk+0][lr]=b0.x; Bs[0][lk+1][lr]=b0.y; Bs[0][lk+2][lr]=b0.z; Bs[0][lk+3][lr]=b0.w;
        Bs[0][lk+4][lr]=b1.x; Bs[0][lk+5][lr]=b1.y; Bs[0][lk+6][lr]=b1.z; Bs[0][lk+7][lr]=b1.w;
    }
    __syncthreads();

    #pragma unroll 1
    for (int t = 0; t < nt; t++) {
        int cur = t & 1;
        float4 a0, a1, b0, b1;
        if (t + 1 < nt) {
            int k0 = (t+1) << 4;
            a0 = *(const float4*)(Ap + k0);
            a1 = *(const float4*)(Ap + k0 + 4);
            b0 = *(const float4*)(Bp + k0);
            b1 = *(const float4*)(Bp + k0 + 4);
        }
        #pragma unroll
        for (int kk = 0; kk < 16; kk++) {
            float4 af0 = *(const float4*)&As[cur][kk][ty*8];
            float4 af1 = *(const float4*)&As[cur][kk][ty*8 + 4];
            ulonglong2 bv0 = *(const ulonglong2*)&Bs[cur][kk][tx*8];
            ulonglong2 bv1 = *(const ulonglong2*)&Bs[cur][kk][tx*8 + 4];
            float av[8] = {af0.x, af0.y, af0.z, af0.w, af1.x, af1.y, af1.z, af1.w};
            unsigned long long bw[4] = {bv0.x, bv0.y, bv1.x, bv1.y};
            #pragma unroll
            for (int i = 0; i < 8; i++) {
                unsigned long long ad = dupf(av[i]);
                #pragma unroll
                for (int j = 0; j < 4; j++) fma2(acc[i][j], ad, bw[j]);
            }
        }
        if (t + 1 < nt) {
            int nb = cur ^ 1;
            As[nb][lk+0][lr]=a0.x; As[nb][lk+1][lr]=a0.y; As[nb][lk+2][lr]=a0.z; As[nb][lk+3][lr]=a0.w;
            As[nb][lk+4][lr]=a1.x; As[nb][lk+5][lr]=a1.y; As[nb][lk+6][lr]=a1.z; As[nb][lk+7][lr]=a1.w;
            Bs[nb][lk+0][lr]=b0.x; Bs[nb][lk+1][lr]=b0.y; Bs[nb][lk+2][lr]=b0.z; Bs[nb][lk+3][lr]=b0.w;
            Bs[nb][lk+4][lr]=b1.x; Bs[nb][lk+5][lr]=b1.y; Bs[nb][lk+6][lr]=b1.z; Bs[nb][lk+7][lr]=b1.w;
        }
        __syncthreads();
    }

    #pragma unroll
    for (int i = 0; i < 8; i++) {
        int m = row0 + ty*8 + i;
        float val[8];
        unpk(acc[i][0], val[0], val[1]); unpk(acc[i][1], val[2], val[3]);
        unpk(acc[i][2], val[4], val[5]); unpk(acc[i][3], val[6], val[7]);
        int n0 = col0 + tx*8;
        const float* bp = g_bcat + n0;
        #pragma unroll
        for (int e = 0; e < 8; e++) val[e] += bp[e];
        int blk = n0 >> 6;
        int w = n0 & 63;
        if (blk == 2) {
            *(float4*)(g_v + (size_t)m*64 + w)     = *(float4*)&val[0];
            *(float4*)(g_v + (size_t)m*64 + w + 4) = *(float4*)&val[4];
        } else {
            __nv_bfloat16* bh;
            __nv_bfloat16* bl;
            if (blk == 0)      { bh = g_qh; bl = g_ql; }
            else if (blk == 1) { bh = g_kh; bl = g_kl; }
            else               { bh = g_ah; bl = g_al;
                #pragma unroll
                for (int e = 0; e < 8; e++) val[e] = 1.f/(1.f+expf(-val[e]));
            }
            __nv_bfloat16 h8[8], l8[8];
            #pragma unroll
            for (int e = 0; e < 8; e++) split_bf16(val[e], h8[e], l8[e]);
            *(uint4*)(bh + (size_t)m*64 + w) = *(uint4*)h8;
            *(uint4*)(bl + (size_t)m*64 + w) = *(uint4*)l8;
        }
    }
}

#define TILEB 18432              /* 128 rows * 144 B */
#define EPI_OFF (4*TILEB)        /* 73728 */

// ---------------- merged A + bin mma-GEMM ----------------
// grid (192, 64): bx<128 -> A tile (alpha @ MT^T -> g_Ah/g_Al split);
//                 bx>=128 -> bin tile (k @ Wd2^T, v-contract -> g_bin).
__global__ void __launch_bounds__(256) hgemmAB() {
    extern __shared__ __align__(16) char smem[];
    uint32_t sb = smem_u32(smem);
    int tid = threadIdx.x;
    int lane = tid & 31, wid = tid >> 5;
    int gid = lane >> 2, tig = lane & 3;
    int warpM = wid >> 2, warpN = wid & 3;
    int m0 = warpM*64, n0 = warpN*32;
    bool isA = blockIdx.x < 128;
    int colIdx = isA ? blockIdx.x : (blockIdx.x - 128);
    int row0 = blockIdx.y*128, col0 = colIdx*128;

    const __nv_bfloat16* opAh = isA ? g_ah  : g_kh;
    const __nv_bfloat16* opAl = isA ? g_al  : g_kl;
    const __nv_bfloat16* opBh = isA ? g_MTh : g_Wd2h;
    const __nv_bfloat16* opBl = isA ? g_MTl : g_Wd2l;

    {
        const uint4* srcs[4] = {
            (const uint4*)(opAh + (size_t)row0*64), (const uint4*)(opAl + (size_t)row0*64),
            (const uint4*)(opBh + (size_t)col0*64), (const uint4*)(opBl + (size_t)col0*64) };
        #pragma unroll
        for (int t = 0; t < 4; t++) {
            char* dst = smem + t*TILEB;
            #pragma unroll
            for (int j = 0; j < 4; j++) {
                int idx = tid + j*256;
                int r = idx >> 3, ch = idx & 7;
                *(uint4*)(dst + r*144 + ch*16) = srcs[t][idx];
            }
        }
    }
    if (!isA) {
        float* sv = (float*)(smem + EPI_OFF);
        const float4* vp = (const float4*)(g_v + (size_t)row0*64);
        #pragma unroll
        for (int j = 0; j < 8; j++) {
            int idx = tid + j*256;
            int r = idx >> 4, q = idx & 15;
            *(float4*)&sv[r*68 + q*4] = vp[idx];
        }
    }
    __syncthreads();

    int q8 = lane >> 3, i8 = lane & 7;
    uint32_t aLane = (uint32_t)(((q8 & 1)*8 + i8)*144 + (q8 >> 1)*16);
    uint32_t bLane = (uint32_t)(((q8 >> 1)*8 + i8)*144 + (q8 & 1)*16);

    float d[4][4][4];
    #pragma unroll
    for (int mt = 0; mt < 4; mt++)
        #pragma unroll
        for (int nt = 0; nt < 4; nt++)
            #pragma unroll
            for (int e = 0; e < 4; e++) d[mt][nt][e] = 0.f;

    #pragma unroll
    for (int term = 0; term < 3; term++) {
        uint32_t aBase = sb + (term == 2 ? TILEB : 0) + (uint32_t)m0*144 + aLane;
        uint32_t bBase = sb + 2*TILEB + (term == 1 ? TILEB : 0) + (uint32_t)n0*144 + bLane;
        #pragma unroll
        for (int ks = 0; ks < 4; ks++) {
            uint32_t koff = (uint32_t)(ks*32);
            uint32_t af[4][4], bf2[2][4];
            #pragma unroll
            for (int mt = 0; mt < 4; mt++)
                LDSM4(af[mt], aBase + mt*16*144 + koff);
            #pragma unroll
            for (int nt2 = 0; nt2 < 2; nt2++)
                LDSM4(bf2[nt2], bBase + nt2*16*144 + koff);
            #pragma unroll
            for (int mt = 0; mt < 4; mt++)
                #pragma unroll
                for (int nt = 0; nt < 4; nt++)
                    MMA16816(d[mt][nt], af[mt], bf2[nt>>1][(nt&1)*2], bf2[nt>>1][(nt&1)*2+1]);
        }
    }
    __syncthreads();

    if (isA) {
        __nv_bfloat16* Dh = (__nv_bfloat16*)smem;              // [128][136]
        __nv_bfloat16* Dl = (__nv_bfloat16*)(smem + 34816);
        #pragma unroll
        for (int mt = 0; mt < 4; mt++) {
            int r0 = m0 + mt*16 + gid, r1 = r0 + 8;
            #pragma unroll
            for (int nt = 0; nt < 4; nt++) {
                int cl = n0 + nt*8 + tig*2;
                __nv_bfloat16 h2[2], l2[2];
                split_bf16(d[mt][nt][0], h2[0], l2[0]);
                split_bf16(d[mt][nt][1], h2[1], l2[1]);
                *(uint32_t*)&Dh[r0*136 + cl] = *(uint32_t*)h2;
                *(uint32_t*)&Dl[r0*136 + cl] = *(uint32_t*)l2;
                split_bf16(d[mt][nt][2], h2[0], l2[0]);
                split_bf16(d[mt][nt][3], h2[1], l2[1]);
                *(uint32_t*)&Dh[r1*136 + cl] = *(uint32_t*)h2;
                *(uint32_t*)&Dl[r1*136 + cl] = *(uint32_t*)l2;
            }
        }
        __syncthreads();
        #pragma unroll
        for (int it = 0; it < 8; it++) {
            int idx = tid + it*256;
            int r = idx >> 4, ch = idx & 15;
            *(uint4*)(g_Ah + (size_t)(row0+r)*16384 + col0 + ch*8) =
                *(const uint4*)((const char*)Dh + r*272 + ch*16);
            *(uint4*)(g_Al + (size_t)(row0+r)*16384 + col0 + ch*8) =
                *(const uint4*)((const char*)Dl + r*272 + ch*16);
        }
    } else {
        const float* sv = (const float*)(smem + EPI_OFF);
        float* red = (float*)smem;
        #pragma unroll
        for (int mt = 0; mt < 4; mt++) {
            int r0 = m0 + mt*16 + gid, r1 = r0 + 8;
            float p0 = 0.f, p1 = 0.f;
            #pragma unroll
            for (int nt = 0; nt < 4; nt++) {
                int v = (n0 + nt*8 + tig*2) & 63;
                p0 += d[mt][nt][0]*sv[r0*68 + v] + d[mt][nt][1]*sv[r0*68 + v + 1];
                p1 += d[mt][nt][2]*sv[r1*68 + v] + d[mt][nt][3]*sv[r1*68 + v + 1];
            }
            p0 += __shfl_xor_sync(0xffffffffu, p0, 1);
            p0 += __shfl_xor_sync(0xffffffffu, p0, 2);
            p1 += __shfl_xor_sync(0xffffffffu, p1, 1);
            p1 += __shfl_xor_sync(0xffffffffu, p1, 2);
            if (tig == 0) { red[r0*4 + warpN] = p0; red[r1*4 + warpN] = p1; }
        }
        __syncthreads();
        if (tid < 128) {
            int cb = colIdx*2;
            float s0 = red[tid*4 + 0] + red[tid*4 + 1];
            float s1 = red[tid*4 + 2] + red[tid*4 + 3];
            g_bin[(size_t)(row0 + tid)*128 + cb]     = s0;
            g_bin[(size_t)(row0 + tid)*128 + cb + 1] = s1;
        }
    }
}

// ---------------- o mma-GEMM (MODE 2 of the old template, standalone) ----------------
__global__ void __launch_bounds__(256) hgemm_o(float* __restrict__ C) {
    extern __shared__ __align__(16) char smem[];
    uint32_t sb = smem_u32(smem);
    int tid = threadIdx.x;
    int lane = tid & 31, wid = tid >> 5;
    int gid = lane >> 2, tig = lane & 3;
    int warpM = wid >> 2, warpN = wid & 3;
    int m0 = warpM*64, n0 = warpN*32;
    int row0 = blockIdx.y*128, col0 = blockIdx.x*128;

    {
        const uint4* srcs[4] = {
            (const uint4*)(g_qh + (size_t)row0*64), (const uint4*)(g_ql + (size_t)row0*64),
            (const uint4*)(g_Wu3h + (size_t)col0*64), (const uint4*)(g_Wu3l + (size_t)col0*64) };
        #pragma unroll
        for (int t = 0; t < 4; t++) {
            char* dst = smem + t*TILEB;
            #pragma unroll
            for (int j = 0; j < 4; j++) {
                int idx = tid + j*256;
                int r = idx >> 3, ch = idx & 7;
                *(uint4*)(dst + r*144 + ch*16) = srcs[t][idx];
            }
        }
    }
    {
        float* sc = (float*)(smem + EPI_OFF);
        const float4* cp = (const float4*)(g_c + (size_t)row0*128);
        #pragma unroll
        for (int j = 0; j < 16; j++) {
            int idx = tid + j*256;
            int r = idx >> 5, q = idx & 31;
            *(float4*)&sc[r*132 + q*4] = cp[idx];
        }
    }
    __syncthreads();

    int q8 = lane >> 3, i8 = lane & 7;
    uint32_t aLane = (uint32_t)(((q8 & 1)*8 + i8)*144 + (q8 >> 1)*16);
    uint32_t bLane = (uint32_t)(((q8 >> 1)*8 + i8)*144 + (q8 & 1)*16);

    float d[4][4][4];
    #pragma unroll
    for (int mt = 0; mt < 4; mt++)
        #pragma unroll
        for (int nt = 0; nt < 4; nt++)
            #pragma unroll
            for (int e = 0; e < 4; e++) d[mt][nt][e] = 0.f;

    #pragma unroll
    for (int term = 0; term < 3; term++) {
        uint32_t aBase = sb + (term == 2 ? TILEB : 0) + (uint32_t)m0*144 + aLane;
        uint32_t bBase = sb + 2*TILEB + (term == 1 ? TILEB : 0) + (uint32_t)n0*144 + bLane;
        #pragma unroll
        for (int ks = 0; ks < 4; ks++) {
            uint32_t koff = (uint32_t)(ks*32);
            uint32_t af[4][4], bf2[2][4];
            #pragma unroll
            for (int mt = 0; mt < 4; mt++)
                LDSM4(af[mt], aBase + mt*16*144 + koff);
            #pragma unroll
            for (int nt2 = 0; nt2 < 2; nt2++)
                LDSM4(bf2[nt2], bBase + nt2*16*144 + koff);
            #pragma unroll
            for (int mt = 0; mt < 4; mt++)
                #pragma unroll
                for (int nt = 0; nt < 4; nt++)
                    MMA16816(d[mt][nt], af[mt], bf2[nt>>1][(nt&1)*2], bf2[nt>>1][(nt&1)*2+1]);
        }
    }
    __syncthreads();

    const float* sc = (const float*)(smem + EPI_OFF);
    float* red = (float*)smem;
    #pragma unroll
    for (int mt = 0; mt < 4; mt++) {
        int r0 = m0 + mt*16 + gid, r1 = r0 + 8;
        float p0 = 0.f, p1 = 0.f;
        #pragma unroll
        for (int nt = 0; nt < 4; nt++) {
            int c = n0 + nt*8 + tig*2;
            p0 += d[mt][nt][0]*sc[r0*132 + c] + d[mt][nt][1]*sc[r0*132 + c + 1];
            p1 += d[mt][nt][2]*sc[r1*132 + c] + d[mt][nt][3]*sc[r1*132 + c + 1];
        }
        p0 += __shfl_xor_sync(0xffffffffu, p0, 1);
        p0 += __shfl_xor_sync(0xffffffffu, p0, 2);
        p1 += __shfl_xor_sync(0xffffffffu, p1, 1);
        p1 += __shfl_xor_sync(0xffffffffu, p1, 2);
        if (tig == 0) { red[r0*4 + warpN] = p0; red[r1*4 + warpN] = p1; }
    }
    __syncthreads();
    if (tid < 128) {
        float s = red[tid*4+0] + red[tid*4+1] + red[tid*4+2] + red[tid*4+3];
        C[(size_t)(row0 + tid)*64 + blockIdx.x] = s;
    }
}

// ---------------- pass A (mma.sync; vectorized d-update) ----------------
#define PA_QH  0         /* bf16 [128][136] = 34816 */
#define PA_QL  34816
#define PA_AB  69632     /* A buffers: buf b -> h at PA_AB + b*69632, l at +34816 */
#define PA_BUFS 69632
#define PA_DS  208896    /* fp32 [2][128] */
#define PA_SMEM 209920
__global__ __launch_bounds__(512) void passA_mma() {
    extern __shared__ __align__(16) char sm[];
    uint32_t sb = smem_u32(sm);
    __nv_bfloat16* sQh = (__nv_bfloat16*)(sm + PA_QH);
    __nv_bfloat16* sQl = (__nv_bfloat16*)(sm + PA_QL);
    float* ds = (float*)(sm + PA_DS);

    int tid = threadIdx.x;
    int lane = tid & 31, wid = tid >> 5;
    int gid = lane >> 2, tig = lane & 3;
    int wm = wid >> 2, wn = wid & 3;
    int chunk = blockIdx.x;
    int b = chunk >> 5, ci = chunk & 31;
    size_t tokBase = (size_t)b*SS + (size_t)ci*CHL;

    for (int idx = tid; idx < 128*136; idx += 512) {
        int r = idx / 136, k = idx - r*136;
        sQh[idx] = __float2bfloat16(r == k ? 1.f : 0.f);
        sQl[idx] = __float2bfloat16(0.f);
    }
    if (tid < 256) ds[tid] = 0.f;

    // prologue: stage A(0) into buf0 (plain ld/st)
    {
        const uint4* Hh = (const uint4*)(g_Ah + tokBase*16384);
        const uint4* Hl = (const uint4*)(g_Al + tokBase*16384);
        #pragma unroll
        for (int j = 0; j < 4; j++) {
            int idx = tid + j*512;
            int r = idx >> 4, ch = idx & 15;
            *(uint4*)(sm + PA_AB + r*272 + ch*16) = Hh[idx];
            *(uint4*)(sm + PA_AB + 34816 + r*272 + ch*16) = Hl[idx];
        }
    }
    __syncthreads();

    int q8 = lane >> 3, i8 = lane & 7;
    uint32_t aLane = (uint32_t)(((q8 & 1)*8 + i8)*272 + (q8 >> 1)*16);
    uint32_t bLane = (uint32_t)(((q8 >> 1)*8 + i8)*272 + (q8 & 1)*16);
    uint32_t qhB = sb + PA_QH + (uint32_t)(wm*32)*272 + aLane;
    uint32_t qlB = sb + PA_QL + (uint32_t)(wm*32)*272 + aLane;

    int drw = tid >> 2, dq = tid & 3;
    int cur = 0;
    for (int s = 0; s < CHL; s++) {
        // 1. prefetch next A into buf cur^1
        if (s + 1 < CHL) {
            const __nv_bfloat16* Hh = g_Ah + (tokBase + s + 1)*16384;
            const __nv_bfloat16* Hl = g_Al + (tokBase + s + 1)*16384;
            uint32_t db = sb + PA_AB + (uint32_t)(cur^1)*PA_BUFS;
            #pragma unroll
            for (int j = 0; j < 4; j++) {
                int idx = tid + j*512;
                int r = idx >> 4, ch = idx & 15;
                CP16(db + r*272 + ch*16, Hh + idx*8);
                CP16(db + 34816 + r*272 + ch*16, Hl + idx*8);
            }
            CP_COMMIT();
        }
        // 2. fp32 d-update from buf cur (vectorized uint4 loads)
        {
            const __nv_bfloat16* ah = (const __nv_bfloat16*)(sm + PA_AB + (size_t)cur*PA_BUFS);
            const __nv_bfloat16* al = ah + 17408;   // +34816 bytes
            const float* dc = ds + cur*128;
            const __nv_bfloat16* ahrow = ah + drw*136;
            const __nv_bfloat16* alrow = al + drw*136;
            float dacc = 0.f;
            #pragma unroll
            for (int q = 0; q < 4; q++) {
                int k0 = dq*32 + q*8;
                uint4 hv = *(const uint4*)(ahrow + k0);
                uint4 lv = *(const uint4*)(alrow + k0);
                float4 c0 = *(const float4*)&dc[k0];
                float4 c1 = *(const float4*)&dc[k0 + 4];
                const __nv_bfloat162* hp = (const __nv_bfloat162*)&hv;
                const __nv_bfloat162* lp = (const __nv_bfloat162*)&lv;
                float2 h0 = __bfloat1622float2(hp[0]), l0 = __bfloat1622float2(lp[0]);
                float2 h1 = __bfloat1622float2(hp[1]), l1 = __bfloat1622float2(lp[1]);
                float2 h2 = __bfloat1622float2(hp[2]), l2 = __bfloat1622float2(lp[2]);
                float2 h3 = __bfloat1622float2(hp[3]), l3 = __bfloat1622float2(lp[3]);
                dacc += (h0.x+l0.x)*c0.x + (h0.y+l0.y)*c0.y
                      + (h1.x+l1.x)*c0.z + (h1.y+l1.y)*c0.w
                      + (h2.x+l2.x)*c1.x + (h2.y+l2.y)*c1.y
                      + (h3.x+l3.x)*c1.z + (h3.y+l3.y)*c1.w;
            }
            dacc += __shfl_xor_sync(0xffffffffu, dacc, 1);
            dacc += __shfl_xor_sync(0xffffffffu, dacc, 2);
            if (dq == 0)
                ds[(cur^1)*128 + drw] = dacc + g_bin[(tokBase + s)*128 + drw];
        }
        // 3. newQ = Q @ A^T, 3-term bf16-split
        uint32_t abse = sb + PA_AB + (uint32_t)cur*PA_BUFS;
        uint32_t ahB = abse + (uint32_t)(wn*32)*272 + bLane;
        uint32_t alB = abse + 34816 + (uint32_t)(wn*32)*272 + bLane;
        float acc[2][4][4];
        #pragma unroll
        for (int mt = 0; mt < 2; mt++)
            #pragma unroll
            for (int nt = 0; nt < 4; nt++)
                #pragma unroll
                for (int e = 0; e < 4; e++) acc[mt][nt][e] = 0.f;
        #pragma unroll
        for (int ks = 0; ks < 8; ks++) {
            uint32_t ko = (uint32_t)(ks*32);
            uint32_t qh[2][4], ql[2][4], ah[2][4], al[2][4];
            #pragma unroll
            for (int mt = 0; mt < 2; mt++) {
                LDSM4(qh[mt], qhB + mt*16*272 + ko);
                LDSM4(ql[mt], qlB + mt*16*272 + ko);
            }
            #pragma unroll
            for (int nb = 0; nb < 2; nb++) {
                LDSM4(ah[nb], ahB + nb*16*272 + ko);
                LDSM4(al[nb], alB + nb*16*272 + ko);
            }
            #pragma unroll
            for (int mt = 0; mt < 2; mt++)
                #pragma unroll
                for (int nt = 0; nt < 4; nt++) {
                    int nb = nt >> 1, hh = (nt & 1)*2;
                    MMA16816(acc[mt][nt], qh[mt], ah[nb][hh], ah[nb][hh+1]);
                    MMA16816(acc[mt][nt], qh[mt], al[nb][hh], al[nb][hh+1]);
                    MMA16816(acc[mt][nt], ql[mt], ah[nb][hh], ah[nb][hh+1]);
                }
        }
        __syncthreads();   // Q reads + d reads complete
        // 4. writeback newQ (bf16 split) or final fp32 to g_P
        if (s + 1 < CHL) {
            #pragma unroll
            for (int mt = 0; mt < 2; mt++)
                #pragma unroll
                for (int nt = 0; nt < 4; nt++) {
                    int r0 = wm*32 + mt*16 + gid, r1 = r0 + 8;
                    int col = wn*32 + nt*8 + tig*2;
                    __nv_bfloat16 hp[2], lp[2];
                    split_bf16(acc[mt][nt][0], hp[0], lp[0]);
                    split_bf16(acc[mt][nt][1], hp[1], lp[1]);
                    *(uint32_t*)&sQh[r0*136 + col] = *(uint32_t*)hp;
                    *(uint32_t*)&sQl[r0*136 + col] = *(uint32_t*)lp;
                    split_bf16(acc[mt][nt][2], hp[0], lp[0]);
                    split_bf16(acc[mt][nt][3], hp[1], lp[1]);
                    *(uint32_t*)&sQh[r1*136 + col] = *(uint32_t*)hp;
                    *(uint32_t*)&sQl[r1*136 + col] = *(uint32_t*)lp;
                }
        } else {
            float* Pout = g_P + (size_t)chunk*16384;
            #pragma unroll
            for (int mt = 0; mt < 2; mt++)
                #pragma unroll
                for (int nt = 0; nt < 4; nt++) {
                    int r0 = wm*32 + mt*16 + gid, r1 = r0 + 8;
                    int col = wn*32 + nt*8 + tig*2;
                    *(float2*)&Pout[r0*128 + col] = make_float2(acc[mt][nt][0], acc[mt][nt][1]);
                    *(float2*)&Pout[r1*128 + col] = make_float2(acc[mt][nt][2], acc[mt][nt][3]);
                }
        }
        CP_WAIT0();
        __syncthreads();
        cur ^= 1;
    }
    if (tid < 128) g_d[chunk*128 + tid] = ds[cur*128 + tid];
}

// ---------------- pass B: cross-chunk scan (reads Q = P^T layout) ----------------
__global__ __launch_bounds__(512) void passB_kern() {
    int b = blockIdx.x;
    int tid = threadIdx.x;
    __shared__ float cv[128], nv[128], red[512];
    if (tid < 128) cv[tid] = 0.f;
    __syncthreads();
    int g = tid >> 7, r = tid & 127;
    for (int i = 0; i < SS/CHL; i++) {
        int chunk = b*(SS/CHL) + i;
        if (tid < 128) g_cb[chunk*128 + tid] = cv[tid];
        __syncthreads();
        const float* Q = g_P + (size_t)chunk*16384;
        float acc = 0.f;
        #pragma unroll 8
        for (int kk = 0; kk < 32; kk++) {
            int k = g*32 + kk;
            acc += Q[k*128 + r] * cv[k];     // P[r][k] = Q[k][r]
        }
        red[g*128 + r] = acc;
        __syncthreads();
        if (tid < 128)
            nv[tid] = red[tid] + red[128+tid] + red[256+tid] + red[384+tid]
                    + g_d[chunk*128 + tid];
        __syncthreads();
        if (tid < 128) cv[tid] = nv[tid];
        __syncthreads();
    }
}

// ---------------- pass C: within-chunk recurrence (bf16 h+l A) ----------------
__global__ __launch_bounds__(512) void passC_kern() {
    int chunk = blockIdx.x;
    int b = chunk >> 5, ci = chunk & 31;
    size_t tokBase = (size_t)b*SS + (size_t)ci*CHL;
    int tid = threadIdx.x;
    int r = tid >> 2, dq = tid & 3;
    __shared__ float cs[2][128];
    if (tid < 128) cs[0][tid] = g_cb[chunk*128 + tid];
    __syncthreads();

    const uint4* Hh = (const uint4*)(g_Ah + tokBase*16384);
    const uint4* Hl = (const uint4*)(g_Al + tokBase*16384);
    int base = r*16 + dq*4;
    uint4 bh[4], bl[4];
    #pragma unroll
    for (int j = 0; j < 4; j++) {
        int pj = (j + dq) & 3;
        bh[j] = Hh[base + pj];
        bl[j] = Hl[base + pj];
    }

    int p = 0;
    for (int s = 0; s < CHL; s++) {
        uint4 nh[4], nl[4];
        if (s + 1 < CHL) {
            const uint4* H2 = Hh + (size_t)(s+1)*2048;
            const uint4* L2 = Hl + (size_t)(s+1)*2048;
            #pragma unroll
            for (int j = 0; j < 4; j++) {
                int pj = (j + dq) & 3;
                nh[j] = H2[base + pj];
                nl[j] = L2[base + pj];
            }
        }
        float acc = 0.f;
        #pragma unroll
        for (int j = 0; j < 4; j++) {
            int pj = (j + dq) & 3;
            const __nv_bfloat162* hp = (const __nv_bfloat162*)&bh[j];
            const __nv_bfloat162* lp = (const __nv_bfloat162*)&bl[j];
            float4 cv0 = *(const float4*)&cs[p][dq*32 + pj*8];
            float4 cv1 = *(const float4*)&cs[p][dq*32 + pj*8 + 4];
            float2 h0 = __bfloat1622float2(hp[0]), l0 = __bfloat1622float2(lp[0]);
            float2 h1 = __bfloat1622float2(hp[1]), l1 = __bfloat1622float2(lp[1]);
            float2 h2 = __bfloat1622float2(hp[2]), l2 = __bfloat1622float2(lp[2]);
            float2 h3 = __bfloat1622float2(hp[3]), l3 = __bfloat1622float2(lp[3]);
            acc += (h0.x+l0.x)*cv0.x + (h0.y+l0.y)*cv0.y
                 + (h1.x+l1.x)*cv0.z + (h1.y+l1.y)*cv0.w
                 + (h2.x+l2.x)*cv1.x + (h2.y+l2.y)*cv1.y
                 + (h3.x+l3.x)*cv1.z + (h3.y+l3.y)*cv1.w;
        }
        acc += __shfl_xor_sync(0xffffffffu, acc, 1);
        acc += __shfl_xor_sync(0xffffffffu, acc, 2);
        if (dq == 0) {
            float cn = acc + g_bin[(tokBase + s)*128 + r];
            cs[p ^ 1][r] = cn;
            g_c[(tokBase + s)*128 + r] = cn;
        }
        __syncthreads();
        p ^= 1;
        #pragma unroll
        for (int j = 0; j < 4; j++) { bh[j] = nh[j]; bl[j] = nl[j]; }
    }
}

// ---------------- host launcher ----------------
extern "C" void kernel_launch(void* const* d_in, const int* in_sizes, int n_in,
                              void* d_out, int out_size) {
    const float* x   = (const float*)d_in[0];
    const float* Wq  = (const float*)d_in[1];
    const float* bq  = (const float*)d_in[2];
    const float* Wk  = (const float*)d_in[3];
    const float* bk  = (const float*)d_in[4];
    const float* Wv  = (const float*)d_in[5];
    const float* bv  = (const float*)d_in[6];
    const float* Wa  = (const float*)d_in[7];
    const float* ba  = (const float*)d_in[8];
    const float* Wdn = (const float*)d_in[9];
    const float* Wup = (const float*)d_in[10];
    float* out = (float*)d_out;

    float *pWcat;
    cudaGetSymbolAddress((void**)&pWcat, g_Wcat);

    cudaFuncSetAttribute(passA_mma, cudaFuncAttributeMaxDynamicSharedMemorySize, PA_SMEM);
    const int SM_AB = EPI_OFF + 128*68*4;    // 108544 (bin path needs sv)
    const int SM_O  = EPI_OFF + 128*132*4;   // 141312
    cudaFuncSetAttribute(hgemmAB, cudaFuncAttributeMaxDynamicSharedMemorySize, SM_AB);
    cudaFuncSetAttribute(hgemm_o, cudaFuncAttributeMaxDynamicSharedMemorySize, SM_O);

    // 1. weight prep (bf16 splits)
    prep_all<<<5184, 256>>>(Wq, bq, Wk, bk, Wv, bv, Wa, ba, Wdn, Wup);
    // 2. projection + split/sigmoid/bf16 epilogue
    gemm_proj<<<dim3(2, 64), 256>>>(x, pWcat, NTOK, 256, DMM);
    // 3. merged A-GEMM + bin-GEMM
    hgemmAB<<<dim3(192, 64), 256, SM_AB>>>();
    // 4. chunk propagators   <-- ncu capture slot
    passA_mma<<<NCH, 512, PA_SMEM>>>();
    // 5. cross-chunk scan
    passB_kern<<<BB, 512>>>();
    // 6. within-chunk recurrence
    passC_kern<<<NCH, 512>>>();
    // 7. o mma-GEMM (q @ Wu3^T, fused c-contraction -> out)
    hgemm_o<<<dim3(64, 64), 256, SM_O>>>(out);
}

// round 14
// speedup vs baseline: 1.0402x; 1.0402x over previous
#include <cuda_runtime.h>
#include <cuda_bf16.h>
#include <math.h>
#include <stdint.h>

#define BB 4
#define SS 2048
#define DMM 1024
#define NTOK (BB*SS)          /* 8192 */
#define CHL 64
#define NCH (NTOK/CHL)        /* 128 */

// ---------------- scratch ----------------
__device__ float g_Wcat[256*DMM];
__device__ float g_bcat[256];
__device__ float g_v[NTOK*64];
__device__ __nv_bfloat16 g_qh[NTOK*64], g_ql[NTOK*64];
__device__ __nv_bfloat16 g_kh[NTOK*64], g_kl[NTOK*64];
__device__ __nv_bfloat16 g_ah[NTOK*64], g_al[NTOK*64];
__device__ __nv_bfloat16 g_MTh[16384*64], g_MTl[16384*64];   // [(c*128+d)][j]
__device__ __nv_bfloat16 g_Wd2h[8192*64], g_Wd2l[8192*64];   // [(c*64+v)][j]
__device__ __nv_bfloat16 g_Wu3h[8192*64], g_Wu3l[8192*64];   // [(v*128+c)][k]
__device__ float g_bin[NTOK*128];
__device__ __nv_bfloat16 g_Ah[(size_t)NTOK*16384];           // 256 MB [t][c*128+d] hi
__device__ __nv_bfloat16 g_Al[(size_t)NTOK*16384];           // 256 MB lo
__device__ float g_P[(size_t)NCH*16384];                     // Q layout: [chunk][n*128+r] = P^T
__device__ float g_d[NCH*128];
__device__ float g_cb[NCH*128];
__device__ float g_c[NTOK*128];

// ---------------- f32x2 helpers ----------------
__device__ __forceinline__ unsigned long long dupf(float a) {
    unsigned long long r;
    asm("mov.b64 %0, {%1, %1};" : "=l"(r) : "f"(a));
    return r;
}
__device__ __forceinline__ void fma2(unsigned long long& c, unsigned long long a, unsigned long long b) {
    asm("fma.rn.f32x2 %0, %1, %2, %0;" : "+l"(c) : "l"(a), "l"(b));
}
__device__ __forceinline__ void unpk(unsigned long long v, float& lo, float& hi) {
    asm("mov.b64 {%0, %1}, %2;" : "=f"(lo), "=f"(hi) : "l"(v));
}

// ---------------- mma helpers ----------------
__device__ __forceinline__ uint32_t smem_u32(const void* p) {
    uint32_t a;
    asm("{ .reg .u64 t; cvta.to.shared.u64 t, %1; cvt.u32.u64 %0, t; }" : "=r"(a) : "l"(p));
    return a;
}
#define LDSM4(r, addr) \
    asm volatile("ldmatrix.sync.aligned.m8n8.x4.shared.b16 {%0,%1,%2,%3}, [%4];" \
        : "=r"((r)[0]), "=r"((r)[1]), "=r"((r)[2]), "=r"((r)[3]) : "r"(addr))
#define MMA16816(d, a, b0, b1) \
    asm volatile("mma.sync.aligned.m16n8k16.row.col.f32.bf16.bf16.f32 " \
        "{%0,%1,%2,%3}, {%4,%5,%6,%7}, {%8,%9}, {%0,%1,%2,%3};" \
        : "+f"((d)[0]), "+f"((d)[1]), "+f"((d)[2]), "+f"((d)[3]) \
        : "r"((a)[0]), "r"((a)[1]), "r"((a)[2]), "r"((a)[3]), "r"(b0), "r"(b1))
#define CP16(dst, src) \
    asm volatile("cp.async.cg.shared.global [%0], [%1], 16;" :: "r"(dst), "l"(src) : "memory")
#define CP_COMMIT() asm volatile("cp.async.commit_group;" ::: "memory")
#define CP_WAIT0()  asm volatile("cp.async.wait_all;" ::: "memory")

__device__ __forceinline__ void split_bf16(float x, __nv_bfloat16& h, __nv_bfloat16& l) {
    h = __float2bfloat16(x);
    l = __float2bfloat16(x - __bfloat162float(h));
}

// ---------------- merged prep (unchanged) ----------------
__global__ __launch_bounds__(256) void prep_all(
        const float* __restrict__ Wq, const float* __restrict__ bq,
        const float* __restrict__ Wk, const float* __restrict__ bk,
        const float* __restrict__ Wv, const float* __restrict__ bv,
        const float* __restrict__ Wa, const float* __restrict__ ba,
        const float* __restrict__ Wd, const float* __restrict__ Wu) {
    __shared__ float sd[128][33];
    __shared__ float su[32][128];
    int bid = blockIdx.x;
    int tid = threadIdx.x;
    if (bid < 64) {
        int j = bid;
        int c0 = tid >> 1;
        int dbase = (tid & 1) * 64;
        float acc[64];
        #pragma unroll
        for (int i = 0; i < 64; i++) acc[i] = 0.f;
        for (int vp = 0; vp < 2; vp++) {
            for (int l = tid; l < 128*32; l += 256) {
                int c = l >> 5, v = l & 31;
                sd[c][v] = Wd[(size_t)c*4096 + j*64 + vp*32 + v];
            }
            for (int l = tid; l < 32*128; l += 256) {
                int v = l >> 7, d = l & 127;
                su[v][d] = Wu[(size_t)(j*64 + vp*32 + v)*128 + d];
            }
            __syncthreads();
            #pragma unroll 8
            for (int v = 0; v < 32; v++) {
                float a = sd[c0][v];
                #pragma unroll
                for (int d = 0; d < 64; d++)
                    acc[d] += a * su[v][dbase + d];
            }
            __syncthreads();
        }
        for (int d = 0; d < 64; d++) {
            __nv_bfloat16 h, l;
            split_bf16(acc[d], h, l);
            size_t pos = (size_t)(c0*128 + dbase + d)*64 + j;
            g_MTh[pos] = h; g_MTl[pos] = l;
        }
    } else if (bid < 1088) {
        int idx = (bid - 64)*256 + tid;
        int r = idx >> 10, cc = idx & 1023;
        float w;
        if (r < 64)       w = Wq[r*DMM + cc];
        else if (r < 128) w = Wk[(r-64)*DMM + cc];
        else if (r < 192) w = Wv[(r-128)*DMM + cc];
        else              w = Wa[(r-192)*DMM + cc];
        g_Wcat[idx] = w;
        if (bid == 64) {
            g_bcat[tid] = (tid < 64) ? bq[tid] :
                          (tid < 128) ? bk[tid-64] :
                          (tid < 192) ? bv[tid-128] : ba[tid-192];
        }
    } else if (bid < 3136) {
        int idx = (bid - 1088)*256 + tid;       // over 128*4096
        int c = idx >> 12, rest = idx & 4095;
        int j = rest >> 6, v = rest & 63;
        __nv_bfloat16 h, l;
        split_bf16(Wd[idx], h, l);
        size_t pos = (size_t)((c<<6) + v)*64 + j;
        g_Wd2h[pos] = h; g_Wd2l[pos] = l;
    } else {
        int idx = (bid - 3136)*256 + tid;       // over 4096*128
        int kv = idx >> 7, c = idx & 127;
        int k = kv >> 6, v = kv & 63;
        __nv_bfloat16 h, l;
        split_bf16(Wu[idx], h, l);
        size_t pos = (size_t)(v*128 + c)*64 + k;
        g_Wu3h[pos] = h; g_Wu3l[pos] = l;
    }
}

// ---------------- projection GEMM (unchanged) ----------------
__global__ void __launch_bounds__(256) gemm_proj(const float* __restrict__ A,
                                                 const float* __restrict__ B,
                                                 int M, int N, int K) {
    __shared__ __align__(16) float As[2][16][132];
    __shared__ __align__(16) float Bs[2][16][132];
    int tid = threadIdx.x;
    int tx = tid & 15, ty = tid >> 4;
    int row0 = blockIdx.y*128, col0 = blockIdx.x*128;
    int lr = tid >> 1;
    int lk = (tid & 1) * 8;
    const float* Ap = A + (size_t)(row0+lr)*K + lk;
    const float* Bp = B + (size_t)(col0+lr)*K + lk;

    unsigned long long acc[8][4];
    #pragma unroll
    for (int i = 0; i < 8; i++)
        #pragma unroll
        for (int j = 0; j < 4; j++) acc[i][j] = 0ULL;

    int nt = K >> 4;
    {
        float4 a0 = *(const float4*)(Ap + 0);
        float4 a1 = *(const float4*)(Ap + 4);
        float4 b0 = *(const float4*)(Bp + 0);
        float4 b1 = *(const float4*)(Bp + 4);
        As[0][lk+0][lr]=a0.x; As[0][lk+1][lr]=a0.y; As[0][lk+2][lr]=a0.z; As[0][lk+3][lr]=a0.w;
        As[0][lk+4][lr]=a1.x; As[0][lk+5][lr]=a1.y; As[0][lk+6][lr]=a1.z; As[0][lk+7][lr]=a1.w;
        Bs[0][lk+0][lr]=b0.x; Bs[0][lk+1][lr]=b0.y; Bs[0][lk+2][lr]=b0.z; Bs[0][lk+3][lr]=b0.w;
        Bs[0][lk+4][lr]=b1.x; Bs[0][lk+5][lr]=b1.y; Bs[0][lk+6][lr]=b1.z; Bs[0][lk+7][lr]=b1.w;
    }
    __syncthreads();

    #pragma unroll 1
    for (int t = 0; t < nt; t++) {
        int cur = t & 1;
        float4 a0, a1, b0, b1;
        if (t + 1 < nt) {
            int k0 = (t+1) << 4;
            a0 = *(const float4*)(Ap + k0);
            a1 = *(const float4*)(Ap + k0 + 4);
            b0 = *(const float4*)(Bp + k0);
            b1 = *(const float4*)(Bp + k0 + 4);
        }
        #pragma unroll
        for (int kk = 0; kk < 16; kk++) {
            float4 af0 = *(const float4*)&As[cur][kk][ty*8];
            float4 af1 = *(const float4*)&As[cur][kk][ty*8 + 4];
            ulonglong2 bv0 = *(const ulonglong2*)&Bs[cur][kk][tx*8];
            ulonglong2 bv1 = *(const ulonglong2*)&Bs[cur][kk][tx*8 + 4];
            float av[8] = {af0.x, af0.y, af0.z, af0.w, af1.x, af1.y, af1.z, af1.w};
            unsigned long long bw[4] = {bv0.x, bv0.y, bv1.x, bv1.y};
            #pragma unroll
            for (int i = 0; i < 8; i++) {
                unsigned long long ad = dupf(av[i]);
                #pragma unroll
                for (int j = 0; j < 4; j++) fma2(acc[i][j], ad, bw[j]);
            }
        }
        if (t + 1 < nt) {
            int nb = cur ^ 1;
            As[nb][lk+0][lr]=a0.x; As[nb][lk+1][lr]=a0.y; As[nb][lk+2][lr]=a0.z; As[nb][lk+3][lr]=a0.w;
            As[nb][lk+4][lr]=a1.x; As[nb][lk+5][lr]=a1.y; As[nb][lk+6][lr]=a1.z; As[nb][lk+7][lr]=a1.w;
            Bs[nb][lk+0][lr]=b0.x; Bs[nb][lk+1][lr]=b0.y; Bs[nb][lk+2][lr]=b0.z; Bs[nb][lk+3][lr]=b0.w;
            Bs[nb][lk+4][lr]=b1.x; Bs[nb][lk+5][lr]=b1.y; Bs[nb][lk+6][lr]=b1.z; Bs[nb][lk+7][lr]=b1.w;
        }
        __syncthreads();
    }

    #pragma unroll
    for (int i = 0; i < 8; i++) {
        int m = row0 + ty*8 + i;
        float val[8];
        unpk(acc[i][0], val[0], val[1]); unpk(acc[i][1], val[2], val[3]);
        unpk(acc[i][2], val[4], val[5]); unpk(acc[i][3], val[6], val[7]);
        int n0 = col0 + tx*8;
        const float* bp = g_bcat + n0;
        #pragma unroll
        for (int e = 0; e < 8; e++) val[e] += bp[e];
        int blk = n0 >> 6;
        int w = n0 & 63;
        if (blk == 2) {
            *(float4*)(g_v + (size_t)m*64 + w)     = *(float4*)&val[0];
            *(float4*)(g_v + (size_t)m*64 + w + 4) = *(float4*)&val[4];
        } else {
            __nv_bfloat16* bh;
            __nv_bfloat16* bl;
            if (blk == 0)      { bh = g_qh; bl = g_ql; }
            else if (blk == 1) { bh = g_kh; bl = g_kl; }
            else               { bh = g_ah; bl = g_al;
                #pragma unroll
                for (int e = 0; e < 8; e++) val[e] = 1.f/(1.f+expf(-val[e]));
            }
            __nv_bfloat16 h8[8], l8[8];
            #pragma unroll
            for (int e = 0; e < 8; e++) split_bf16(val[e], h8[e], l8[e]);
            *(uint4*)(bh + (size_t)m*64 + w) = *(uint4*)h8;
            *(uint4*)(bl + (size_t)m*64 + w) = *(uint4*)l8;
        }
    }
}

// ---------------- mma.sync bf16-split K=64 GEMM (R12 template, reverted) ----------------
#define TILEB 18432              /* 128 rows * 144 B */
#define EPI_OFF (4*TILEB)        /* 73728 */
template<int MODE>
__global__ void __launch_bounds__(256) hgemm(const __nv_bfloat16* __restrict__ Ah,
                                             const __nv_bfloat16* __restrict__ Al,
                                             const __nv_bfloat16* __restrict__ Bh,
                                             const __nv_bfloat16* __restrict__ Bl,
                                             float* __restrict__ C) {
    extern __shared__ __align__(16) char smem[];
    uint32_t sb = smem_u32(smem);
    int tid = threadIdx.x;
    int lane = tid & 31, wid = tid >> 5;
    int gid = lane >> 2, tig = lane & 3;
    int warpM = wid >> 2, warpN = wid & 3;
    int m0 = warpM*64, n0 = warpN*32;
    int row0 = blockIdx.y*128, col0 = blockIdx.x*128;

    {
        const uint4* srcs[4] = {
            (const uint4*)(Ah + (size_t)row0*64), (const uint4*)(Al + (size_t)row0*64),
            (const uint4*)(Bh + (size_t)col0*64), (const uint4*)(Bl + (size_t)col0*64) };
        #pragma unroll
        for (int t = 0; t < 4; t++) {
            char* dst = smem + t*TILEB;
            #pragma unroll
            for (int j = 0; j < 4; j++) {
                int idx = tid + j*256;
                int r = idx >> 3, ch = idx & 7;
                *(uint4*)(dst + r*144 + ch*16) = srcs[t][idx];
            }
        }
    }
    if (MODE == 1) {
        float* sv = (float*)(smem + EPI_OFF);
        const float4* vp = (const float4*)(g_v + (size_t)row0*64);
        #pragma unroll
        for (int j = 0; j < 8; j++) {
            int idx = tid + j*256;
            int r = idx >> 4, q = idx & 15;
            *(float4*)&sv[r*68 + q*4] = vp[idx];
        }
    }
    if (MODE == 2) {
        float* sc = (float*)(smem + EPI_OFF);
        const float4* cp = (const float4*)(g_c + (size_t)row0*128);
        #pragma unroll
        for (int j = 0; j < 16; j++) {
            int idx = tid + j*256;
            int r = idx >> 5, q = idx & 31;
            *(float4*)&sc[r*132 + q*4] = cp[idx];
        }
    }
    __syncthreads();

    int q8 = lane >> 3, i8 = lane & 7;
    uint32_t aLane = (uint32_t)(((q8 & 1)*8 + i8)*144 + (q8 >> 1)*16);
    uint32_t bLane = (uint32_t)(((q8 >> 1)*8 + i8)*144 + (q8 & 1)*16);

    float d[4][4][4];
    #pragma unroll
    for (int mt = 0; mt < 4; mt++)
        #pragma unroll
        for (int nt = 0; nt < 4; nt++)
            #pragma unroll
            for (int e = 0; e < 4; e++) d[mt][nt][e] = 0.f;

    #pragma unroll
    for (int term = 0; term < 3; term++) {
        uint32_t aBase = sb + (term == 2 ? TILEB : 0) + (uint32_t)m0*144 + aLane;
        uint32_t bBase = sb + 2*TILEB + (term == 1 ? TILEB : 0) + (uint32_t)n0*144 + bLane;
        #pragma unroll
        for (int ks = 0; ks < 4; ks++) {
            uint32_t koff = (uint32_t)(ks*32);
            uint32_t af[4][4], bf2[2][4];
            #pragma unroll
            for (int mt = 0; mt < 4; mt++)
                LDSM4(af[mt], aBase + mt*16*144 + koff);
            #pragma unroll
            for (int nt2 = 0; nt2 < 2; nt2++)
                LDSM4(bf2[nt2], bBase + nt2*16*144 + koff);
            #pragma unroll
            for (int mt = 0; mt < 4; mt++)
                #pragma unroll
                for (int nt = 0; nt < 4; nt++)
                    MMA16816(d[mt][nt], af[mt], bf2[nt>>1][(nt&1)*2], bf2[nt>>1][(nt&1)*2+1]);
        }
    }
    __syncthreads();

    if (MODE == 0) {
        __nv_bfloat16* Dh = (__nv_bfloat16*)smem;              // [128][136]
        __nv_bfloat16* Dl = (__nv_bfloat16*)(smem + 34816);
        #pragma unroll
        for (int mt = 0; mt < 4; mt++) {
            int r0 = m0 + mt*16 + gid, r1 = r0 + 8;
            #pragma unroll
            for (int nt = 0; nt < 4; nt++) {
                int cl = n0 + nt*8 + tig*2;
                __nv_bfloat16 h2[2], l2[2];
                split_bf16(d[mt][nt][0], h2[0], l2[0]);
                split_bf16(d[mt][nt][1], h2[1], l2[1]);
                *(uint32_t*)&Dh[r0*136 + cl] = *(uint32_t*)h2;
                *(uint32_t*)&Dl[r0*136 + cl] = *(uint32_t*)l2;
                split_bf16(d[mt][nt][2], h2[0], l2[0]);
                split_bf16(d[mt][nt][3], h2[1], l2[1]);
                *(uint32_t*)&Dh[r1*136 + cl] = *(uint32_t*)h2;
                *(uint32_t*)&Dl[r1*136 + cl] = *(uint32_t*)l2;
            }
        }
        __syncthreads();
        #pragma unroll
        for (int it = 0; it < 8; it++) {
            int idx = tid + it*256;
            int r = idx >> 4, ch = idx & 15;
            *(uint4*)(g_Ah + (size_t)(row0+r)*16384 + col0 + ch*8) =
                *(const uint4*)((const char*)Dh + r*272 + ch*16);
            *(uint4*)(g_Al + (size_t)(row0+r)*16384 + col0 + ch*8) =
                *(const uint4*)((const char*)Dl + r*272 + ch*16);
        }
    } else if (MODE == 1) {
        const float* sv = (const float*)(smem + EPI_OFF);
        float* red = (float*)smem;
        #pragma unroll
        for (int mt = 0; mt < 4; mt++) {
            int r0 = m0 + mt*16 + gid, r1 = r0 + 8;
            float p0 = 0.f, p1 = 0.f;
            #pragma unroll
            for (int nt = 0; nt < 4; nt++) {
                int v = (n0 + nt*8 + tig*2) & 63;
                p0 += d[mt][nt][0]*sv[r0*68 + v] + d[mt][nt][1]*sv[r0*68 + v + 1];
                p1 += d[mt][nt][2]*sv[r1*68 + v] + d[mt][nt][3]*sv[r1*68 + v + 1];
            }
            p0 += __shfl_xor_sync(0xffffffffu, p0, 1);
            p0 += __shfl_xor_sync(0xffffffffu, p0, 2);
            p1 += __shfl_xor_sync(0xffffffffu, p1, 1);
            p1 += __shfl_xor_sync(0xffffffffu, p1, 2);
            if (tig == 0) { red[r0*4 + warpN] = p0; red[r1*4 + warpN] = p1; }
        }
        __syncthreads();
        if (tid < 128) {
            int cb = blockIdx.x*2;
            float s0 = red[tid*4 + 0] + red[tid*4 + 1];
            float s1 = red[tid*4 + 2] + red[tid*4 + 3];
            g_bin[(size_t)(row0 + tid)*128 + cb]     = s0;
            g_bin[(size_t)(row0 + tid)*128 + cb + 1] = s1;
        }
    } else {
        const float* sc = (const float*)(smem + EPI_OFF);
        float* red = (float*)smem;
        #pragma unroll
        for (int mt = 0; mt < 4; mt++) {
            int r0 = m0 + mt*16 + gid, r1 = r0 + 8;
            float p0 = 0.f, p1 = 0.f;
            #pragma unroll
            for (int nt = 0; nt < 4; nt++) {
                int c = n0 + nt*8 + tig*2;
                p0 += d[mt][nt][0]*sc[r0*132 + c] + d[mt][nt][1]*sc[r0*132 + c + 1];
                p1 += d[mt][nt][2]*sc[r1*132 + c] + d[mt][nt][3]*sc[r1*132 + c + 1];
            }
            p0 += __shfl_xor_sync(0xffffffffu, p0, 1);
            p0 += __shfl_xor_sync(0xffffffffu, p0, 2);
            p1 += __shfl_xor_sync(0xffffffffu, p1, 1);
            p1 += __shfl_xor_sync(0xffffffffu, p1, 2);
            if (tig == 0) { red[r0*4 + warpN] = p0; red[r1*4 + warpN] = p1; }
        }
        __syncthreads();
        if (tid < 128) {
            float s = red[tid*4+0] + red[tid*4+1] + red[tid*4+2] + red[tid*4+3];
            C[(size_t)(row0 + tid)*64 + blockIdx.x] = s;
        }
    }
}

// ---------------- pass A (mma.sync; 1024 threads / 32 warps for latency hiding) ----------------
#define PA_QH  0         /* bf16 [128][136] = 34816 */
#define PA_QL  34816
#define PA_AB  69632     /* A buffers: buf b -> h at PA_AB + b*69632, l at +34816 */
#define PA_BUFS 69632
#define PA_DS  208896    /* fp32 [2][128] */
#define PA_SMEM 209920
__global__ __launch_bounds__(1024) void passA_mma() {
    extern __shared__ __align__(16) char sm[];
    uint32_t sb = smem_u32(sm);
    __nv_bfloat16* sQh = (__nv_bfloat16*)(sm + PA_QH);
    __nv_bfloat16* sQl = (__nv_bfloat16*)(sm + PA_QL);
    float* ds = (float*)(sm + PA_DS);

    int tid = threadIdx.x;
    int lane = tid & 31, wid = tid >> 5;       // 32 warps
    int gid = lane >> 2, tig = lane & 3;
    int wm = wid >> 2;                         // 0..7 : 16-row slab
    int wn = wid & 3;                          // 0..3 : 32-col slab
    int chunk = blockIdx.x;
    int b = chunk >> 5, ci = chunk & 31;
    size_t tokBase = (size_t)b*SS + (size_t)ci*CHL;

    for (int idx = tid; idx < 128*136; idx += 1024) {
        int r = idx / 136, k = idx - r*136;
        sQh[idx] = __float2bfloat16(r == k ? 1.f : 0.f);
        sQl[idx] = __float2bfloat16(0.f);
    }
    if (tid < 256) ds[tid] = 0.f;

    // prologue: stage A(0) into buf0 (plain ld/st)
    {
        const uint4* Hh = (const uint4*)(g_Ah + tokBase*16384);
        const uint4* Hl = (const uint4*)(g_Al + tokBase*16384);
        #pragma unroll
        for (int j = 0; j < 2; j++) {
            int idx = tid + j*1024;
            int r = idx >> 4, ch = idx & 15;
            *(uint4*)(sm + PA_AB + r*272 + ch*16) = Hh[idx];
            *(uint4*)(sm + PA_AB + 34816 + r*272 + ch*16) = Hl[idx];
        }
    }
    __syncthreads();

    int q8 = lane >> 3, i8 = lane & 7;
    uint32_t aLane = (uint32_t)(((q8 & 1)*8 + i8)*272 + (q8 >> 1)*16);
    uint32_t bLane = (uint32_t)(((q8 >> 1)*8 + i8)*272 + (q8 & 1)*16);
    uint32_t qhB = sb + PA_QH + (uint32_t)(wm*16)*272 + aLane;
    uint32_t qlB = sb + PA_QL + (uint32_t)(wm*16)*272 + aLane;

    int drw = tid >> 3, dq8 = tid & 7;         // 8 lanes per d-row, 16 k each
    int cur = 0;
    for (int s = 0; s < CHL; s++) {
        // 1. prefetch next A into buf cur^1
        if (s + 1 < CHL) {
            const __nv_bfloat16* Hh = g_Ah + (tokBase + s + 1)*16384;
            const __nv_bfloat16* Hl = g_Al + (tokBase + s + 1)*16384;
            uint32_t db = sb + PA_AB + (uint32_t)(cur^1)*PA_BUFS;
            #pragma unroll
            for (int j = 0; j < 2; j++) {
                int idx = tid + j*1024;
                int r = idx >> 4, ch = idx & 15;
                CP16(db + r*272 + ch*16, Hh + idx*8);
                CP16(db + 34816 + r*272 + ch*16, Hl + idx*8);
            }
            CP_COMMIT();
        }
        // 2. fp32 d-update from buf cur (vectorized; 8 lanes/row, 16 k each)
        {
            const __nv_bfloat16* ah = (const __nv_bfloat16*)(sm + PA_AB + (size_t)cur*PA_BUFS);
            const __nv_bfloat16* al = ah + 17408;   // +34816 bytes
            const float* dc = ds + cur*128;
            const __nv_bfloat16* ahrow = ah + drw*136;
            const __nv_bfloat16* alrow = al + drw*136;
            float dacc = 0.f;
            #pragma unroll
            for (int q = 0; q < 2; q++) {
                int k0 = dq8*16 + q*8;
                uint4 hv = *(const uint4*)(ahrow + k0);
                uint4 lv = *(const uint4*)(alrow + k0);
                float4 c0 = *(const float4*)&dc[k0];
                float4 c1 = *(const float4*)&dc[k0 + 4];
                const __nv_bfloat162* hp = (const __nv_bfloat162*)&hv;
                const __nv_bfloat162* lp = (const __nv_bfloat162*)&lv;
                float2 h0 = __bfloat1622float2(hp[0]), l0 = __bfloat1622float2(lp[0]);
                float2 h1 = __bfloat1622float2(hp[1]), l1 = __bfloat1622float2(lp[1]);
                float2 h2 = __bfloat1622float2(hp[2]), l2 = __bfloat1622float2(lp[2]);
                float2 h3 = __bfloat1622float2(hp[3]), l3 = __bfloat1622float2(lp[3]);
                dacc += (h0.x+l0.x)*c0.x + (h0.y+l0.y)*c0.y
                      + (h1.x+l1.x)*c0.z + (h1.y+l1.y)*c0.w
                      + (h2.x+l2.x)*c1.x + (h2.y+l2.y)*c1.y
                      + (h3.x+l3.x)*c1.z + (h3.y+l3.y)*c1.w;
            }
            dacc += __shfl_xor_sync(0xffffffffu, dacc, 1);
            dacc += __shfl_xor_sync(0xffffffffu, dacc, 2);
            dacc += __shfl_xor_sync(0xffffffffu, dacc, 4);
            if (dq8 == 0)
                ds[(cur^1)*128 + drw] = dacc + g_bin[(tokBase + s)*128 + drw];
        }
        // 3. newQ = Q @ A^T, 3-term bf16-split (warp tile 16x32)
        uint32_t abse = sb + PA_AB + (uint32_t)cur*PA_BUFS;
        uint32_t ahB = abse + (uint32_t)(wn*32)*272 + bLane;
        uint32_t alB = abse + 34816 + (uint32_t)(wn*32)*272 + bLane;
        float acc[4][4];
        #pragma unroll
        for (int nt = 0; nt < 4; nt++)
            #pragma unroll
            for (int e = 0; e < 4; e++) acc[nt][e] = 0.f;
        #pragma unroll
        for (int ks = 0; ks < 8; ks++) {
            uint32_t ko = (uint32_t)(ks*32);
            uint32_t qh[4], ql[4], ah[2][4], al[2][4];
            LDSM4(qh, qhB + ko);
            LDSM4(ql, qlB + ko);
            #pragma unroll
            for (int nb = 0; nb < 2; nb++) {
                LDSM4(ah[nb], ahB + nb*16*272 + ko);
                LDSM4(al[nb], alB + nb*16*272 + ko);
            }
            #pragma unroll
            for (int nt = 0; nt < 4; nt++) {
                int nb = nt >> 1, hh = (nt & 1)*2;
                MMA16816(acc[nt], qh, ah[nb][hh], ah[nb][hh+1]);
                MMA16816(acc[nt], qh, al[nb][hh], al[nb][hh+1]);
                MMA16816(acc[nt], ql, ah[nb][hh], ah[nb][hh+1]);
            }
        }
        __syncthreads();   // Q reads + d reads complete
        // 4. writeback newQ (bf16 split) or final fp32 to g_P
        if (s + 1 < CHL) {
            #pragma unroll
            for (int nt = 0; nt < 4; nt++) {
                int r0 = wm*16 + gid, r1 = r0 + 8;
                int col = wn*32 + nt*8 + tig*2;
                __nv_bfloat16 hp[2], lp[2];
                split_bf16(acc[nt][0], hp[0], lp[0]);
                split_bf16(acc[nt][1], hp[1], lp[1]);
                *(uint32_t*)&sQh[r0*136 + col] = *(uint32_t*)hp;
                *(uint32_t*)&sQl[r0*136 + col] = *(uint32_t*)lp;
                split_bf16(acc[nt][2], hp[0], lp[0]);
                split_bf16(acc[nt][3], hp[1], lp[1]);
                *(uint32_t*)&sQh[r1*136 + col] = *(uint32_t*)hp;
                *(uint32_t*)&sQl[r1*136 + col] = *(uint32_t*)lp;
            }
        } else {
            float* Pout = g_P + (size_t)chunk*16384;
            #pragma unroll
            for (int nt = 0; nt < 4; nt++) {
                int r0 = wm*16 + gid, r1 = r0 + 8;
                int col = wn*32 + nt*8 + tig*2;
                *(float2*)&Pout[r0*128 + col] = make_float2(acc[nt][0], acc[nt][1]);
                *(float2*)&Pout[r1*128 + col] = make_float2(acc[nt][2], acc[nt][3]);
            }
        }
        CP_WAIT0();
        __syncthreads();
        cur ^= 1;
    }
    if (tid < 128) g_d[chunk*128 + tid] = ds[cur*128 + tid];
}

// ---------------- pass B: cross-chunk scan (reads Q = P^T layout) ----------------
__global__ __launch_bounds__(512) void passB_kern() {
    int b = blockIdx.x;
    int tid = threadIdx.x;
    __shared__ float cv[128], nv[128], red[512];
    if (tid < 128) cv[tid] = 0.f;
    __syncthreads();
    int g = tid >> 7, r = tid & 127;
    for (int i = 0; i < SS/CHL; i++) {
        int chunk = b*(SS/CHL) + i;
        if (tid < 128) g_cb[chunk*128 + tid] = cv[tid];
        __syncthreads();
        const float* Q = g_P + (size_t)chunk*16384;
        float acc = 0.f;
        #pragma unroll 8
        for (int kk = 0; kk < 32; kk++) {
            int k = g*32 + kk;
            acc += Q[k*128 + r] * cv[k];     // P[r][k] = Q[k][r]
        }
        red[g*128 + r] = acc;
        __syncthreads();
        if (tid < 128)
            nv[tid] = red[tid] + red[128+tid] + red[256+tid] + red[384+tid]
                    + g_d[chunk*128 + tid];
        __syncthreads();
        if (tid < 128) cv[tid] = nv[tid];
        __syncthreads();
    }
}

// ---------------- pass C: within-chunk recurrence (bf16 h+l A) ----------------
__global__ __launch_bounds__(512) void passC_kern() {
    int chunk = blockIdx.x;
    int b = chunk >> 5, ci = chunk & 31;
    size_t tokBase = (size_t)b*SS + (size_t)ci*CHL;
    int tid = threadIdx.x;
    int r = tid >> 2, dq = tid & 3;
    __shared__ float cs[2][128];
    if (tid < 128) cs[0][tid] = g_cb[chunk*128 + tid];
    __syncthreads();

    const uint4* Hh = (const uint4*)(g_Ah + tokBase*16384);
    const uint4* Hl = (const uint4*)(g_Al + tokBase*16384);
    int base = r*16 + dq*4;
    uint4 bh[4], bl[4];
    #pragma unroll
    for (int j = 0; j < 4; j++) {
        int pj = (j + dq) & 3;
        bh[j] = Hh[base + pj];
        bl[j] = Hl[base + pj];
    }

    int p = 0;
    for (int s = 0; s < CHL; s++) {
        uint4 nh[4], nl[4];
        if (s + 1 < CHL) {
            const uint4* H2 = Hh + (size_t)(s+1)*2048;
            const uint4* L2 = Hl + (size_t)(s+1)*2048;
            #pragma unroll
            for (int j = 0; j < 4; j++) {
                int pj = (j + dq) & 3;
                nh[j] = H2[base + pj];
                nl[j] = L2[base + pj];
            }
        }
        float acc = 0.f;
        #pragma unroll
        for (int j = 0; j < 4; j++) {
            int pj = (j + dq) & 3;
            const __nv_bfloat162* hp = (const __nv_bfloat162*)&bh[j];
            const __nv_bfloat162* lp = (const __nv_bfloat162*)&bl[j];
            float4 cv0 = *(const float4*)&cs[p][dq*32 + pj*8];
            float4 cv1 = *(const float4*)&cs[p][dq*32 + pj*8 + 4];
            float2 h0 = __bfloat1622float2(hp[0]), l0 = __bfloat1622float2(lp[0]);
            float2 h1 = __bfloat1622float2(hp[1]), l1 = __bfloat1622float2(lp[1]);
            float2 h2 = __bfloat1622float2(hp[2]), l2 = __bfloat1622float2(lp[2]);
            float2 h3 = __bfloat1622float2(hp[3]), l3 = __bfloat1622float2(lp[3]);
            acc += (h0.x+l0.x)*cv0.x + (h0.y+l0.y)*cv0.y
                 + (h1.x+l1.x)*cv0.z + (h1.y+l1.y)*cv0.w
                 + (h2.x+l2.x)*cv1.x + (h2.y+l2.y)*cv1.y
                 + (h3.x+l3.x)*cv1.z + (h3.y+l3.y)*cv1.w;
        }
        acc += __shfl_xor_sync(0xffffffffu, acc, 1);
        acc += __shfl_xor_sync(0xffffffffu, acc, 2);
        if (dq == 0) {
            float cn = acc + g_bin[(tokBase + s)*128 + r];
            cs[p ^ 1][r] = cn;
            g_c[(tokBase + s)*128 + r] = cn;
        }
        __syncthreads();
        p ^= 1;
        #pragma unroll
        for (int j = 0; j < 4; j++) { bh[j] = nh[j]; bl[j] = nl[j]; }
    }
}

// ---------------- host launcher ----------------
extern "C" void kernel_launch(void* const* d_in, const int* in_sizes, int n_in,
                              void* d_out, int out_size) {
    const float* x   = (const float*)d_in[0];
    const float* Wq  = (const float*)d_in[1];
    const float* bq  = (const float*)d_in[2];
    const float* Wk  = (const float*)d_in[3];
    const float* bk  = (const float*)d_in[4];
    const float* Wv  = (const float*)d_in[5];
    const float* bv  = (const float*)d_in[6];
    const float* Wa  = (const float*)d_in[7];
    const float* ba  = (const float*)d_in[8];
    const float* Wdn = (const float*)d_in[9];
    const float* Wup = (const float*)d_in[10];
    float* out = (float*)d_out;

    float *pWcat;
    __nv_bfloat16 *pQh, *pQl, *pKh, *pKl, *pAh, *pAl, *pMTh, *pMTl, *pWd2h, *pWd2l, *pWu3h, *pWu3l;
    cudaGetSymbolAddress((void**)&pWcat, g_Wcat);
    cudaGetSymbolAddress((void**)&pQh,   g_qh);
    cudaGetSymbolAddress((void**)&pQl,   g_ql);
    cudaGetSymbolAddress((void**)&pKh,   g_kh);
    cudaGetSymbolAddress((void**)&pKl,   g_kl);
    cudaGetSymbolAddress((void**)&pAh,   g_ah);
    cudaGetSymbolAddress((void**)&pAl,   g_al);
    cudaGetSymbolAddress((void**)&pMTh,  g_MTh);
    cudaGetSymbolAddress((void**)&pMTl,  g_MTl);
    cudaGetSymbolAddress((void**)&pWd2h, g_Wd2h);
    cudaGetSymbolAddress((void**)&pWd2l, g_Wd2l);
    cudaGetSymbolAddress((void**)&pWu3h, g_Wu3h);
    cudaGetSymbolAddress((void**)&pWu3l, g_Wu3l);

    cudaFuncSetAttribute(passA_mma, cudaFuncAttributeMaxDynamicSharedMemorySize, PA_SMEM);

    const int SM0 = EPI_OFF;                 // 73728
    const int SM1 = EPI_OFF + 128*68*4;      // 108544
    const int SM2 = EPI_OFF + 128*132*4;     // 141312
    cudaFuncSetAttribute(hgemm<0>, cudaFuncAttributeMaxDynamicSharedMemorySize, SM0);
    cudaFuncSetAttribute(hgemm<1>, cudaFuncAttributeMaxDynamicSharedMemorySize, SM1);
    cudaFuncSetAttribute(hgemm<2>, cudaFuncAttributeMaxDynamicSharedMemorySize, SM2);

    // 1. weight prep (bf16 splits)
    prep_all<<<5184, 256>>>(Wq, bq, Wk, bk, Wv, bv, Wa, ba, Wdn, Wup);
    // 2. projection + split/sigmoid/bf16 epilogue
    gemm_proj<<<dim3(2, 64), 256>>>(x, pWcat, NTOK, 256, DMM);
    // 3. bin mma-GEMM (k @ Wd2^T, fused v-contraction -> g_bin)
    hgemm<1><<<dim3(64, 64), 256, SM1>>>(pKh, pKl, pWd2h, pWd2l, nullptr);
    // 4. A mma-GEMM (alpha @ MT^T -> g_Ah/g_Al split)   <-- ncu capture slot
    hgemm<0><<<dim3(128, 64), 256, SM0>>>(pAh, pAl, pMTh, pMTl, nullptr);
    // 5. chunk propagators (32 warps)
    passA_mma<<<NCH, 1024, PA_SMEM>>>();
    // 6. cross-chunk scan
    passB_kern<<<BB, 512>>>();
    // 7. within-chunk recurrence
    passC_kern<<<NCH, 512>>>();
    // 8. o mma-GEMM (q @ Wu3^T, fused c-contraction -> out)
    hgemm<2><<<dim3(64, 64), 256, SM2>>>(pQh, pQl, pWu3h, pWu3l, out);
}

// round 17
// speedup vs baseline: 1.0619x; 1.0208x over previous
#include <cuda_runtime.h>
#include <cuda_bf16.h>
#include <math.h>
#include <stdint.h>

// R17 — rebase on R12-passing source; sole delta: vectorized d-update in passA
// (block itself runtime-proven inside R14/R15 benches).

#define BB 4
#define SS 2048
#define DMM 1024
#define NTOK (BB*SS)          /* 8192 */
#define CHL 64
#define NCH (NTOK/CHL)        /* 128 */

// ---------------- scratch ----------------
__device__ float g_Wcat[256*DMM];
__device__ float g_bcat[256];
__device__ float g_v[NTOK*64];
__device__ __nv_bfloat16 g_qh[NTOK*64], g_ql[NTOK*64];
__device__ __nv_bfloat16 g_kh[NTOK*64], g_kl[NTOK*64];
__device__ __nv_bfloat16 g_ah[NTOK*64], g_al[NTOK*64];
__device__ __nv_bfloat16 g_MTh[16384*64], g_MTl[16384*64];   // [(c*128+d)][j]
__device__ __nv_bfloat16 g_Wd2h[8192*64], g_Wd2l[8192*64];   // [(c*64+v)][j]
__device__ __nv_bfloat16 g_Wu3h[8192*64], g_Wu3l[8192*64];   // [(v*128+c)][k]
__device__ float g_bin[NTOK*128];
__device__ __nv_bfloat16 g_Ah[(size_t)NTOK*16384];           // 256 MB [t][c*128+d] hi
__device__ __nv_bfloat16 g_Al[(size_t)NTOK*16384];           // 256 MB lo
__device__ float g_P[(size_t)NCH*16384];                     // Q layout: [chunk][n*128+r] = P^T
__device__ float g_d[NCH*128];
__device__ float g_cb[NCH*128];
__device__ float g_c[NTOK*128];

// ---------------- f32x2 helpers ----------------
__device__ __forceinline__ unsigned long long dupf(float a) {
    unsigned long long r;
    asm("mov.b64 %0, {%1, %1};" : "=l"(r) : "f"(a));
    return r;
}
__device__ __forceinline__ void fma2(unsigned long long& c, unsigned long long a, unsigned long long b) {
    asm("fma.rn.f32x2 %0, %1, %2, %0;" : "+l"(c) : "l"(a), "l"(b));
}
__device__ __forceinline__ void unpk(unsigned long long v, float& lo, float& hi) {
    asm("mov.b64 {%0, %1}, %2;" : "=f"(lo), "=f"(hi) : "l"(v));
}

// ---------------- mma helpers ----------------
__device__ __forceinline__ uint32_t smem_u32(const void* p) {
    uint32_t a;
    asm("{ .reg .u64 t; cvta.to.shared.u64 t, %1; cvt.u32.u64 %0, t; }" : "=r"(a) : "l"(p));
    return a;
}
#define LDSM4(r, addr) \
    asm volatile("ldmatrix.sync.aligned.m8n8.x4.shared.b16 {%0,%1,%2,%3}, [%4];" \
        : "=r"((r)[0]), "=r"((r)[1]), "=r"((r)[2]), "=r"((r)[3]) : "r"(addr))
#define MMA16816(d, a, b0, b1) \
    asm volatile("mma.sync.aligned.m16n8k16.row.col.f32.bf16.bf16.f32 " \
        "{%0,%1,%2,%3}, {%4,%5,%6,%7}, {%8,%9}, {%0,%1,%2,%3};" \
        : "+f"((d)[0]), "+f"((d)[1]), "+f"((d)[2]), "+f"((d)[3]) \
        : "r"((a)[0]), "r"((a)[1]), "r"((a)[2]), "r"((a)[3]), "r"(b0), "r"(b1))
#define CP16(dst, src) \
    asm volatile("cp.async.cg.shared.global [%0], [%1], 16;" :: "r"(dst), "l"(src) : "memory")
#define CP_COMMIT() asm volatile("cp.async.commit_group;" ::: "memory")
#define CP_WAIT0()  asm volatile("cp.async.wait_all;" ::: "memory")

__device__ __forceinline__ void split_bf16(float x, __nv_bfloat16& h, __nv_bfloat16& l) {
    h = __float2bfloat16(x);
    l = __float2bfloat16(x - __bfloat162float(h));
}

// ---------------- merged prep ----------------
__global__ __launch_bounds__(256) void prep_all(
        const float* __restrict__ Wq, const float* __restrict__ bq,
        const float* __restrict__ Wk, const float* __restrict__ bk,
        const float* __restrict__ Wv, const float* __restrict__ bv,
        const float* __restrict__ Wa, const float* __restrict__ ba,
        const float* __restrict__ Wd, const float* __restrict__ Wu) {
    __shared__ float sd[128][33];
    __shared__ float su[32][128];
    int bid = blockIdx.x;
    int tid = threadIdx.x;
    if (bid < 64) {
        int j = bid;
        int c0 = tid >> 1;
        int dbase = (tid & 1) * 64;
        float acc[64];
        #pragma unroll
        for (int i = 0; i < 64; i++) acc[i] = 0.f;
        for (int vp = 0; vp < 2; vp++) {
            for (int l = tid; l < 128*32; l += 256) {
                int c = l >> 5, v = l & 31;
                sd[c][v] = Wd[(size_t)c*4096 + j*64 + vp*32 + v];
            }
            for (int l = tid; l < 32*128; l += 256) {
                int v = l >> 7, d = l & 127;
                su[v][d] = Wu[(size_t)(j*64 + vp*32 + v)*128 + d];
            }
            __syncthreads();
            #pragma unroll 8
            for (int v = 0; v < 32; v++) {
                float a = sd[c0][v];
                #pragma unroll
                for (int d = 0; d < 64; d++)
                    acc[d] += a * su[v][dbase + d];
            }
            __syncthreads();
        }
        for (int d = 0; d < 64; d++) {
            __nv_bfloat16 h, l;
            split_bf16(acc[d], h, l);
            size_t pos = (size_t)(c0*128 + dbase + d)*64 + j;
            g_MTh[pos] = h; g_MTl[pos] = l;
        }
    } else if (bid < 1088) {
        int idx = (bid - 64)*256 + tid;
        int r = idx >> 10, cc = idx & 1023;
        float w;
        if (r < 64)       w = Wq[r*DMM + cc];
        else if (r < 128) w = Wk[(r-64)*DMM + cc];
        else if (r < 192) w = Wv[(r-128)*DMM + cc];
        else              w = Wa[(r-192)*DMM + cc];
        g_Wcat[idx] = w;
        if (bid == 64) {
            g_bcat[tid] = (tid < 64) ? bq[tid] :
                          (tid < 128) ? bk[tid-64] :
                          (tid < 192) ? bv[tid-128] : ba[tid-192];
        }
    } else if (bid < 3136) {
        int idx = (bid - 1088)*256 + tid;       // over 128*4096
        int c = idx >> 12, rest = idx & 4095;
        int j = rest >> 6, v = rest & 63;
        __nv_bfloat16 h, l;
        split_bf16(Wd[idx], h, l);
        size_t pos = (size_t)((c<<6) + v)*64 + j;
        g_Wd2h[pos] = h; g_Wd2l[pos] = l;
    } else {
        int idx = (bid - 3136)*256 + tid;       // over 4096*128
        int kv = idx >> 7, c = idx & 127;
        int k = kv >> 6, v = kv & 63;
        __nv_bfloat16 h, l;
        split_bf16(Wu[idx], h, l);
        size_t pos = (size_t)(v*128 + c)*64 + k;
        g_Wu3h[pos] = h; g_Wu3l[pos] = l;
    }
}

// ---------------- projection GEMM (K=1024, fp32 f32x2), split/sigmoid/bf16 epilogue ----------------
__global__ void __launch_bounds__(256) gemm_proj(const float* __restrict__ A,
                                                 const float* __restrict__ B,
                                                 int M, int N, int K) {
    __shared__ __align__(16) float As[2][16][132];
    __shared__ __align__(16) float Bs[2][16][132];
    int tid = threadIdx.x;
    int tx = tid & 15, ty = tid >> 4;
    int row0 = blockIdx.y*128, col0 = blockIdx.x*128;
    int lr = tid >> 1;
    int lk = (tid & 1) * 8;
    const float* Ap = A + (size_t)(row0+lr)*K + lk;
    const float* Bp = B + (size_t)(col0+lr)*K + lk;

    unsigned long long acc[8][4];
    #pragma unroll
    for (int i = 0; i < 8; i++)
        #pragma unroll
        for (int j = 0; j < 4; j++) acc[i][j] = 0ULL;

    int nt = K >> 4;
    {
        float4 a0 = *(const float4*)(Ap + 0);
        float4 a1 = *(const float4*)(Ap + 4);
        float4 b0 = *(const float4*)(Bp + 0);
        float4 b1 = *(const float4*)(Bp + 4);
        As[0][lk+0][lr]=a0.x; As[0][lk+1][lr]=a0.y; As[0][lk+2][lr]=a0.z; As[0][lk+3][lr]=a0.w;
        As[0][lk+4][lr]=a1.x; As[0][lk+5][lr]=a1.y; As[0][lk+6][lr]=a1.z; As[0][lk+7][lr]=a1.w;
        Bs[0][lk+0][lr]=b0.x; Bs[0][lk+1][lr]=b0.y; Bs[0][lk+2][lr]=b0.z; Bs[0][lk+3][lr]=b0.w;
        Bs[0][lk+4][lr]=b1.x; Bs[0][lk+5][lr]=b1.y; Bs[0][lk+6][lr]=b1.z; Bs[0][lk+7][lr]=b1.w;
    }
    __syncthreads();

    #pragma unroll 1
    for (int t = 0; t < nt; t++) {
        int cur = t & 1;
        float4 a0, a1, b0, b1;
        if (t + 1 < nt) {
            int k0 = (t+1) << 4;
            a0 = *(const float4*)(Ap + k0);
            a1 = *(const float4*)(Ap + k0 + 4);
            b0 = *(const float4*)(Bp + k0);
            b1 = *(const float4*)(Bp + k0 + 4);
        }
        #pragma unroll
        for (int kk = 0; kk < 16; kk++) {
            float4 af0 = *(const float4*)&As[cur][kk][ty*8];
            float4 af1 = *(const float4*)&As[cur][kk][ty*8 + 4];
            ulonglong2 bv0 = *(const ulonglong2*)&Bs[cur][kk][tx*8];
            ulonglong2 bv1 = *(const ulonglong2*)&Bs[cur][kk][tx*8 + 4];
            float av[8] = {af0.x, af0.y, af0.z, af0.w, af1.x, af1.y, af1.z, af1.w};
            unsigned long long bw[4] = {bv0.x, bv0.y, bv1.x, bv1.y};
            #pragma unroll
            for (int i = 0; i < 8; i++) {
                unsigned long long ad = dupf(av[i]);
                #pragma unroll
                for (int j = 0; j < 4; j++) fma2(acc[i][j], ad, bw[j]);
            }
        }
        if (t + 1 < nt) {
            int nb = cur ^ 1;
            As[nb][lk+0][lr]=a0.x; As[nb][lk+1][lr]=a0.y; As[nb][lk+2][lr]=a0.z; As[nb][lk+3][lr]=a0.w;
            As[nb][lk+4][lr]=a1.x; As[nb][lk+5][lr]=a1.y; As[nb][lk+6][lr]=a1.z; As[nb][lk+7][lr]=a1.w;
            Bs[nb][lk+0][lr]=b0.x; Bs[nb][lk+1][lr]=b0.y; Bs[nb][lk+2][lr]=b0.z; Bs[nb][lk+3][lr]=b0.w;
            Bs[nb][lk+4][lr]=b1.x; Bs[nb][lk+5][lr]=b1.y; Bs[nb][lk+6][lr]=b1.z; Bs[nb][lk+7][lr]=b1.w;
        }
        __syncthreads();
    }

    #pragma unroll
    for (int i = 0; i < 8; i++) {
        int m = row0 + ty*8 + i;
        float val[8];
        unpk(acc[i][0], val[0], val[1]); unpk(acc[i][1], val[2], val[3]);
        unpk(acc[i][2], val[4], val[5]); unpk(acc[i][3], val[6], val[7]);
        int n0 = col0 + tx*8;
        const float* bp = g_bcat + n0;
        #pragma unroll
        for (int e = 0; e < 8; e++) val[e] += bp[e];
        int blk = n0 >> 6;
        int w = n0 & 63;
        if (blk == 2) {
            *(float4*)(g_v + (size_t)m*64 + w)     = *(float4*)&val[0];
            *(float4*)(g_v + (size_t)m*64 + w + 4) = *(float4*)&val[4];
        } else {
            __nv_bfloat16* bh;
            __nv_bfloat16* bl;
            if (blk == 0)      { bh = g_qh; bl = g_ql; }
            else if (blk == 1) { bh = g_kh; bl = g_kl; }
            else               { bh = g_ah; bl = g_al;
                #pragma unroll
                for (int e = 0; e < 8; e++) val[e] = 1.f/(1.f+expf(-val[e]));
            }
            __nv_bfloat16 h8[8], l8[8];
            #pragma unroll
            for (int e = 0; e < 8; e++) split_bf16(val[e], h8[e], l8[e]);
            *(uint4*)(bh + (size_t)m*64 + w) = *(uint4*)h8;
            *(uint4*)(bl + (size_t)m*64 + w) = *(uint4*)l8;
        }
    }
}

// ---------------- mma.sync bf16-split K=64 GEMM ----------------
#define TILEB 18432              /* 128 rows * 144 B */
#define EPI_OFF (4*TILEB)        /* 73728 */
template<int MODE>
__global__ void __launch_bounds__(256) hgemm(const __nv_bfloat16* __restrict__ Ah,
                                             const __nv_bfloat16* __restrict__ Al,
                                             const __nv_bfloat16* __restrict__ Bh,
                                             const __nv_bfloat16* __restrict__ Bl,
                                             float* __restrict__ C) {
    extern __shared__ __align__(16) char smem[];
    uint32_t sb = smem_u32(smem);
    int tid = threadIdx.x;
    int lane = tid & 31, wid = tid >> 5;
    int gid = lane >> 2, tig = lane & 3;
    int warpM = wid >> 2, warpN = wid & 3;
    int m0 = warpM*64, n0 = warpN*32;
    int row0 = blockIdx.y*128, col0 = blockIdx.x*128;

    {
        const uint4* srcs[4] = {
            (const uint4*)(Ah + (size_t)row0*64), (const uint4*)(Al + (size_t)row0*64),
            (const uint4*)(Bh + (size_t)col0*64), (const uint4*)(Bl + (size_t)col0*64) };
        #pragma unroll
        for (int t = 0; t < 4; t++) {
            char* dst = smem + t*TILEB;
            #pragma unroll
            for (int j = 0; j < 4; j++) {
                int idx = tid + j*256;
                int r = idx >> 3, ch = idx & 7;
                *(uint4*)(dst + r*144 + ch*16) = srcs[t][idx];
            }
        }
    }
    if (MODE == 1) {
        float* sv = (float*)(smem + EPI_OFF);
        const float4* vp = (const float4*)(g_v + (size_t)row0*64);
        #pragma unroll
        for (int j = 0; j < 8; j++) {
            int idx = tid + j*256;
            int r = idx >> 4, q = idx & 15;
            *(float4*)&sv[r*68 + q*4] = vp[idx];
        }
    }
    if (MODE == 2) {
        float* sc = (float*)(smem + EPI_OFF);
        const float4* cp = (const float4*)(g_c + (size_t)row0*128);
        #pragma unroll
        for (int j = 0; j < 16; j++) {
            int idx = tid + j*256;
            int r = idx >> 5, q = idx & 31;
            *(float4*)&sc[r*132 + q*4] = cp[idx];
        }
    }
    __syncthreads();

    int q8 = lane >> 3, i8 = lane & 7;
    uint32_t aLane = (uint32_t)(((q8 & 1)*8 + i8)*144 + (q8 >> 1)*16);
    uint32_t bLane = (uint32_t)(((q8 >> 1)*8 + i8)*144 + (q8 & 1)*16);

    float d[4][4][4];
    #pragma unroll
    for (int mt = 0; mt < 4; mt++)
        #pragma unroll
        for (int nt = 0; nt < 4; nt++)
            #pragma unroll
            for (int e = 0; e < 4; e++) d[mt][nt][e] = 0.f;

    #pragma unroll
    for (int term = 0; term < 3; term++) {
        uint32_t aBase = sb + (term == 2 ? TILEB : 0) + (uint32_t)m0*144 + aLane;
        uint32_t bBase = sb + 2*TILEB + (term == 1 ? TILEB : 0) + (uint32_t)n0*144 + bLane;
        #pragma unroll
        for (int ks = 0; ks < 4; ks++) {
            uint32_t koff = (uint32_t)(ks*32);
            uint32_t af[4][4], bf2[2][4];
            #pragma unroll
            for (int mt = 0; mt < 4; mt++)
                LDSM4(af[mt], aBase + mt*16*144 + koff);
            #pragma unroll
            for (int nt2 = 0; nt2 < 2; nt2++)
                LDSM4(bf2[nt2], bBase + nt2*16*144 + koff);
            #pragma unroll
            for (int mt = 0; mt < 4; mt++)
                #pragma unroll
                for (int nt = 0; nt < 4; nt++)
                    MMA16816(d[mt][nt], af[mt], bf2[nt>>1][(nt&1)*2], bf2[nt>>1][(nt&1)*2+1]);
        }
    }
    __syncthreads();

    if (MODE == 0) {
        __nv_bfloat16* Dh = (__nv_bfloat16*)smem;              // [128][136]
        __nv_bfloat16* Dl = (__nv_bfloat16*)(smem + 34816);
        #pragma unroll
        for (int mt = 0; mt < 4; mt++) {
            int r0 = m0 + mt*16 + gid, r1 = r0 + 8;
            #pragma unroll
            for (int nt = 0; nt < 4; nt++) {
                int cl = n0 + nt*8 + tig*2;
                __nv_bfloat16 h2[2], l2[2];
                split_bf16(d[mt][nt][0], h2[0], l2[0]);
                split_bf16(d[mt][nt][1], h2[1], l2[1]);
                *(uint32_t*)&Dh[r0*136 + cl] = *(uint32_t*)h2;
                *(uint32_t*)&Dl[r0*136 + cl] = *(uint32_t*)l2;
                split_bf16(d[mt][nt][2], h2[0], l2[0]);
                split_bf16(d[mt][nt][3], h2[1], l2[1]);
                *(uint32_t*)&Dh[r1*136 + cl] = *(uint32_t*)h2;
                *(uint32_t*)&Dl[r1*136 + cl] = *(uint32_t*)l2;
            }
        }
        __syncthreads();
        #pragma unroll
        for (int it = 0; it < 8; it++) {
            int idx = tid + it*256;
            int r = idx >> 4, ch = idx & 15;
            *(uint4*)(g_Ah + (size_t)(row0+r)*16384 + col0 + ch*8) =
                *(const uint4*)((const char*)Dh + r*272 + ch*16);
            *(uint4*)(g_Al + (size_t)(row0+r)*16384 + col0 + ch*8) =
                *(const uint4*)((const char*)Dl + r*272 + ch*16);
        }
    } else if (MODE == 1) {
        const float* sv = (const float*)(smem + EPI_OFF);
        float* red = (float*)smem;
        #pragma unroll
        for (int mt = 0; mt < 4; mt++) {
            int r0 = m0 + mt*16 + gid, r1 = r0 + 8;
            float p0 = 0.f, p1 = 0.f;
            #pragma unroll
            for (int nt = 0; nt < 4; nt++) {
                int v = (n0 + nt*8 + tig*2) & 63;
                p0 += d[mt][nt][0]*sv[r0*68 + v] + d[mt][nt][1]*sv[r0*68 + v + 1];
                p1 += d[mt][nt][2]*sv[r1*68 + v] + d[mt][nt][3]*sv[r1*68 + v + 1];
            }
            p0 += __shfl_xor_sync(0xffffffffu, p0, 1);
            p0 += __shfl_xor_sync(0xffffffffu, p0, 2);
            p1 += __shfl_xor_sync(0xffffffffu, p1, 1);
            p1 += __shfl_xor_sync(0xffffffffu, p1, 2);
            if (tig == 0) { red[r0*4 + warpN] = p0; red[r1*4 + warpN] = p1; }
        }
        __syncthreads();
        if (tid < 128) {
            int cb = blockIdx.x*2;
            float s0 = red[tid*4 + 0] + red[tid*4 + 1];
            float s1 = red[tid*4 + 2] + red[tid*4 + 3];
            g_bin[(size_t)(row0 + tid)*128 + cb]     = s0;
            g_bin[(size_t)(row0 + tid)*128 + cb + 1] = s1;
        }
    } else {
        const float* sc = (const float*)(smem + EPI_OFF);
        float* red = (float*)smem;
        #pragma unroll
        for (int mt = 0; mt < 4; mt++) {
            int r0 = m0 + mt*16 + gid, r1 = r0 + 8;
            float p0 = 0.f, p1 = 0.f;
            #pragma unroll
            for (int nt = 0; nt < 4; nt++) {
                int c = n0 + nt*8 + tig*2;
                p0 += d[mt][nt][0]*sc[r0*132 + c] + d[mt][nt][1]*sc[r0*132 + c + 1];
                p1 += d[mt][nt][2]*sc[r1*132 + c] + d[mt][nt][3]*sc[r1*132 + c + 1];
            }
            p0 += __shfl_xor_sync(0xffffffffu, p0, 1);
            p0 += __shfl_xor_sync(0xffffffffu, p0, 2);
            p1 += __shfl_xor_sync(0xffffffffu, p1, 1);
            p1 += __shfl_xor_sync(0xffffffffu, p1, 2);
            if (tig == 0) { red[r0*4 + warpN] = p0; red[r1*4 + warpN] = p1; }
        }
        __syncthreads();
        if (tid < 128) {
            float s = red[tid*4+0] + red[tid*4+1] + red[tid*4+2] + red[tid*4+3];
            C[(size_t)(row0 + tid)*64 + blockIdx.x] = s;
        }
    }
}

// ---------------- pass A (512 threads, hardened, vectorized d-update) ----------------
#define PA_QH  0
#define PA_QL  34816
#define PA_AB  69632
#define PA_BUFS 69632
#define PA_DS  208896
#define PA_SMEM 209920
__global__ __launch_bounds__(512) void passA_mma() {
    extern __shared__ __align__(16) char sm[];
    uint32_t sb = smem_u32(sm);
    __nv_bfloat16* sQh = (__nv_bfloat16*)(sm + PA_QH);
    __nv_bfloat16* sQl = (__nv_bfloat16*)(sm + PA_QL);
    float* ds = (float*)(sm + PA_DS);

    int tid = threadIdx.x;
    int lane = tid & 31, wid = tid >> 5;
    int gid = lane >> 2, tig = lane & 3;
    int wm = wid >> 2, wn = wid & 3;
    int chunk = blockIdx.x;
    int b = chunk >> 5, ci = chunk & 31;
    size_t tokBase = (size_t)b*SS + (size_t)ci*CHL;

    for (int idx = tid; idx < 128*136; idx += 512) {
        int r = idx / 136, k = idx - r*136;
        sQh[idx] = __float2bfloat16(r == k ? 1.f : 0.f);
        sQl[idx] = __float2bfloat16(0.f);
    }
    if (tid < 256) ds[tid] = 0.f;

    // prologue: stage A(0) into buf0 (plain ld/st)
    {
        const uint4* Hh = (const uint4*)(g_Ah + tokBase*16384);
        const uint4* Hl = (const uint4*)(g_Al + tokBase*16384);
        #pragma unroll
        for (int j = 0; j < 4; j++) {
            int idx = tid + j*512;
            int r = idx >> 4, ch = idx & 15;
            *(uint4*)(sm + PA_AB + r*272 + ch*16) = Hh[idx];
            *(uint4*)(sm + PA_AB + 34816 + r*272 + ch*16) = Hl[idx];
        }
    }
    __syncthreads();

    int q8 = lane >> 3, i8 = lane & 7;
    uint32_t aLane = (uint32_t)(((q8 & 1)*8 + i8)*272 + (q8 >> 1)*16);
    uint32_t bLane = (uint32_t)(((q8 >> 1)*8 + i8)*272 + (q8 & 1)*16);
    uint32_t qhB = sb + PA_QH + (uint32_t)(wm*32)*272 + aLane;
    uint32_t qlB = sb + PA_QL + (uint32_t)(wm*32)*272 + aLane;

    int drw = tid >> 2, dq = tid & 3;
    int cur = 0;
    for (int s = 0; s < CHL; s++) {
        // 1. prefetch next A into buf cur^1
        if (s + 1 < CHL) {
            const __nv_bfloat16* Hh = g_Ah + (tokBase + s + 1)*16384;
            const __nv_bfloat16* Hl = g_Al + (tokBase + s + 1)*16384;
            uint32_t db = sb + PA_AB + (uint32_t)(cur^1)*PA_BUFS;
            #pragma unroll
            for (int j = 0; j < 4; j++) {
                int idx = tid + j*512;
                int r = idx >> 4, ch = idx & 15;
                CP16(db + r*272 + ch*16, Hh + idx*8);
                CP16(db + 34816 + r*272 + ch*16, Hl + idx*8);
            }
            CP_COMMIT();
        }
        // 2. fp32 d-update from buf cur (vectorized uint4 loads)
        {
            const __nv_bfloat16* ah = (const __nv_bfloat16*)(sm + PA_AB + (size_t)cur*PA_BUFS);
            const __nv_bfloat16* al = ah + 17408;   // +34816 bytes
            const float* dc = ds + cur*128;
            const __nv_bfloat16* ahrow = ah + drw*136;
            const __nv_bfloat16* alrow = al + drw*136;
            float dacc = 0.f;
            #pragma unroll
            for (int q = 0; q < 4; q++) {
                int k0 = dq*32 + q*8;
                uint4 hv = *(const uint4*)(ahrow + k0);
                uint4 lv = *(const uint4*)(alrow + k0);
                float4 c0 = *(const float4*)&dc[k0];
                float4 c1 = *(const float4*)&dc[k0 + 4];
                const __nv_bfloat162* hp = (const __nv_bfloat162*)&hv;
                const __nv_bfloat162* lp = (const __nv_bfloat162*)&lv;
                float2 h0 = __bfloat1622float2(hp[0]), l0 = __bfloat1622float2(lp[0]);
                float2 h1 = __bfloat1622float2(hp[1]), l1 = __bfloat1622float2(lp[1]);
                float2 h2 = __bfloat1622float2(hp[2]), l2 = __bfloat1622float2(lp[2]);
                float2 h3 = __bfloat1622float2(hp[3]), l3 = __bfloat1622float2(lp[3]);
                dacc += (h0.x+l0.x)*c0.x + (h0.y+l0.y)*c0.y
                      + (h1.x+l1.x)*c0.z + (h1.y+l1.y)*c0.w
                      + (h2.x+l2.x)*c1.x + (h2.y+l2.y)*c1.y
                      + (h3.x+l3.x)*c1.z + (h3.y+l3.y)*c1.w;
            }
            dacc += __shfl_xor_sync(0xffffffffu, dacc, 1);
            dacc += __shfl_xor_sync(0xffffffffu, dacc, 2);
            if (dq == 0)
                ds[(cur^1)*128 + drw] = dacc + g_bin[(tokBase + s)*128 + drw];
        }
        // 3. newQ = Q @ A^T, 3-term bf16-split
        uint32_t abse = sb + PA_AB + (uint32_t)cur*PA_BUFS;
        uint32_t ahB = abse + (uint32_t)(wn*32)*272 + bLane;
        uint32_t alB = abse + 34816 + (uint32_t)(wn*32)*272 + bLane;
        float acc[2][4][4];
        #pragma unroll
        for (int mt = 0; mt < 2; mt++)
            #pragma unroll
            for (int nt = 0; nt < 4; nt++)
                #pragma unroll
                for (int e = 0; e < 4; e++) acc[mt][nt][e] = 0.f;
        #pragma unroll
        for (int ks = 0; ks < 8; ks++) {
            uint32_t ko = (uint32_t)(ks*32);
            uint32_t qh[2][4], ql[2][4], ah[2][4], al[2][4];
            #pragma unroll
            for (int mt = 0; mt < 2; mt++) {
                LDSM4(qh[mt], qhB + mt*16*272 + ko);
                LDSM4(ql[mt], qlB + mt*16*272 + ko);
            }
            #pragma unroll
            for (int nb = 0; nb < 2; nb++) {
                LDSM4(ah[nb], ahB + nb*16*272 + ko);
                LDSM4(al[nb], alB + nb*16*272 + ko);
            }
            #pragma unroll
            for (int mt = 0; mt < 2; mt++)
                #pragma unroll
                for (int nt = 0; nt < 4; nt++) {
                    int nb = nt >> 1, hh = (nt & 1)*2;
                    MMA16816(acc[mt][nt], qh[mt], ah[nb][hh], ah[nb][hh+1]);
                    MMA16816(acc[mt][nt], qh[mt], al[nb][hh], al[nb][hh+1]);
                    MMA16816(acc[mt][nt], ql[mt], ah[nb][hh], ah[nb][hh+1]);
                }
        }
        __syncthreads();
        // 4. writeback newQ (bf16 split) or final fp32 to g_P
        if (s + 1 < CHL) {
            #pragma unroll
            for (int mt = 0; mt < 2; mt++)
                #pragma unroll
                for (int nt = 0; nt < 4; nt++) {
                    int r0 = wm*32 + mt*16 + gid, r1 = r0 + 8;
                    int col = wn*32 + nt*8 + tig*2;
                    __nv_bfloat16 hp[2], lp[2];
                    split_bf16(acc[mt][nt][0], hp[0], lp[0]);
                    split_bf16(acc[mt][nt][1], hp[1], lp[1]);
                    *(uint32_t*)&sQh[r0*136 + col] = *(uint32_t*)hp;
                    *(uint32_t*)&sQl[r0*136 + col] = *(uint32_t*)lp;
                    split_bf16(acc[mt][nt][2], hp[0], lp[0]);
                    split_bf16(acc[mt][nt][3], hp[1], lp[1]);
                    *(uint32_t*)&sQh[r1*136 + col] = *(uint32_t*)hp;
                    *(uint32_t*)&sQl[r1*136 + col] = *(uint32_t*)lp;
                }
        } else {
            float* Pout = g_P + (size_t)chunk*16384;
            #pragma unroll
            for (int mt = 0; mt < 2; mt++)
                #pragma unroll
                for (int nt = 0; nt < 4; nt++) {
                    int r0 = wm*32 + mt*16 + gid, r1 = r0 + 8;
                    int col = wn*32 + nt*8 + tig*2;
                    *(float2*)&Pout[r0*128 + col] = make_float2(acc[mt][nt][0], acc[mt][nt][1]);
                    *(float2*)&Pout[r1*128 + col] = make_float2(acc[mt][nt][2], acc[mt][nt][3]);
                }
        }
        CP_WAIT0();
        __syncthreads();
        cur ^= 1;
    }
    if (tid < 128) g_d[chunk*128 + tid] = ds[cur*128 + tid];
}

// ---------------- pass B ----------------
__global__ __launch_bounds__(512) void passB_kern() {
    int b = blockIdx.x;
    int tid = threadIdx.x;
    __shared__ float cv[128], nv[128], red[512];
    if (tid < 128) cv[tid] = 0.f;
    __syncthreads();
    int g = tid >> 7, r = tid & 127;
    for (int i = 0; i < SS/CHL; i++) {
        int chunk = b*(SS/CHL) + i;
        if (tid < 128) g_cb[chunk*128 + tid] = cv[tid];
        __syncthreads();
        const float* Q = g_P + (size_t)chunk*16384;
        float acc = 0.f;
        #pragma unroll 8
        for (int kk = 0; kk < 32; kk++) {
            int k = g*32 + kk;
            acc += Q[k*128 + r] * cv[k];     // P[r][k] = Q[k][r]
        }
        red[g*128 + r] = acc;
        __syncthreads();
        if (tid < 128)
            nv[tid] = red[tid] + red[128+tid] + red[256+tid] + red[384+tid]
                    + g_d[chunk*128 + tid];
        __syncthreads();
        if (tid < 128) cv[tid] = nv[tid];
        __syncthreads();
    }
}

// ---------------- pass C ----------------
__global__ __launch_bounds__(512) void passC_kern() {
    int chunk = blockIdx.x;
    int b = chunk >> 5, ci = chunk & 31;
    size_t tokBase = (size_t)b*SS + (size_t)ci*CHL;
    int tid = threadIdx.x;
    int r = tid >> 2, dq = tid & 3;
    __shared__ float cs[2][128];
    if (tid < 128) cs[0][tid] = g_cb[chunk*128 + tid];
    __syncthreads();

    const uint4* Hh = (const uint4*)(g_Ah + tokBase*16384);
    const uint4* Hl = (const uint4*)(g_Al + tokBase*16384);
    int base = r*16 + dq*4;
    uint4 bh[4], bl[4];
    #pragma unroll
    for (int j = 0; j < 4; j++) {
        int pj = (j + dq) & 3;
        bh[j] = Hh[base + pj];
        bl[j] = Hl[base + pj];
    }

    int p = 0;
    for (int s = 0; s < CHL; s++) {
        uint4 nh[4], nl[4];
        if (s + 1 < CHL) {
            const uint4* H2 = Hh + (size_t)(s+1)*2048;
            const uint4* L2 = Hl + (size_t)(s+1)*2048;
            #pragma unroll
            for (int j = 0; j < 4; j++) {
                int pj = (j + dq) & 3;
                nh[j] = H2[base + pj];
                nl[j] = L2[base + pj];
            }
        }
        float acc = 0.f;
        #pragma unroll
        for (int j = 0; j < 4; j++) {
            int pj = (j + dq) & 3;
            const __nv_bfloat162* hp = (const __nv_bfloat162*)&bh[j];
            const __nv_bfloat162* lp = (const __nv_bfloat162*)&bl[j];
            float4 cv0 = *(const float4*)&cs[p][dq*32 + pj*8];
            float4 cv1 = *(const float4*)&cs[p][dq*32 + pj*8 + 4];
            float2 h0 = __bfloat1622float2(hp[0]), l0 = __bfloat1622float2(lp[0]);
            float2 h1 = __bfloat1622float2(hp[1]), l1 = __bfloat1622float2(lp[1]);
            float2 h2 = __bfloat1622float2(hp[2]), l2 = __bfloat1622float2(lp[2]);
            float2 h3 = __bfloat1622float2(hp[3]), l3 = __bfloat1622float2(lp[3]);
            acc += (h0.x+l0.x)*cv0.x + (h0.y+l0.y)*cv0.y
                 + (h1.x+l1.x)*cv0.z + (h1.y+l1.y)*cv0.w
                 + (h2.x+l2.x)*cv1.x + (h2.y+l2.y)*cv1.y
                 + (h3.x+l3.x)*cv1.z + (h3.y+l3.y)*cv1.w;
        }
        acc += __shfl_xor_sync(0xffffffffu, acc, 1);
        acc += __shfl_xor_sync(0xffffffffu, acc, 2);
        if (dq == 0) {
            float cn = acc + g_bin[(tokBase + s)*128 + r];
            cs[p ^ 1][r] = cn;
            g_c[(tokBase + s)*128 + r] = cn;
        }
        __syncthreads();
        p ^= 1;
        #pragma unroll
        for (int j = 0; j < 4; j++) { bh[j] = nh[j]; bl[j] = nl[j]; }
    }
}

// ---------------- host launcher ----------------
extern "C" void kernel_launch(void* const* d_in, const int* in_sizes, int n_in,
                              void* d_out, int out_size) {
    const float* x   = (const float*)d_in[0];
    const float* Wq  = (const float*)d_in[1];
    const float* bq  = (const float*)d_in[2];
    const float* Wk  = (const float*)d_in[3];
    const float* bk  = (const float*)d_in[4];
    const float* Wv  = (const float*)d_in[5];
    const float* bv  = (const float*)d_in[6];
    const float* Wa  = (const float*)d_in[7];
    const float* ba  = (const float*)d_in[8];
    const float* Wdn = (const float*)d_in[9];
    const float* Wup = (const float*)d_in[10];
    float* out = (float*)d_out;

    float *pWcat;
    __nv_bfloat16 *pQh, *pQl, *pKh, *pKl, *pAh, *pAl, *pMTh, *pMTl, *pWd2h, *pWd2l, *pWu3h, *pWu3l;
    cudaGetSymbolAddress((void**)&pWcat, g_Wcat);
    cudaGetSymbolAddress((void**)&pQh,   g_qh);
    cudaGetSymbolAddress((void**)&pQl,   g_ql);
    cudaGetSymbolAddress((void**)&pKh,   g_kh);
    cudaGetSymbolAddress((void**)&pKl,   g_kl);
    cudaGetSymbolAddress((void**)&pAh,   g_ah);
    cudaGetSymbolAddress((void**)&pAl,   g_al);
    cudaGetSymbolAddress((void**)&pMTh,  g_MTh);
    cudaGetSymbolAddress((void**)&pMTl,  g_MTl);
    cudaGetSymbolAddress((void**)&pWd2h, g_Wd2h);
    cudaGetSymbolAddress((void**)&pWd2l, g_Wd2l);
    cudaGetSymbolAddress((void**)&pWu3h, g_Wu3h);
    cudaGetSymbolAddress((void**)&pWu3l, g_Wu3l);

    cudaFuncSetAttribute(passA_mma, cudaFuncAttributeMaxDynamicSharedMemorySize, PA_SMEM);
    const int SM0 = EPI_OFF;                 // 73728
    const int SM1 = EPI_OFF + 128*68*4;      // 108544
    const int SM2 = EPI_OFF + 128*132*4;     // 141312
    cudaFuncSetAttribute(hgemm<0>, cudaFuncAttributeMaxDynamicSharedMemorySize, SM0);
    cudaFuncSetAttribute(hgemm<1>, cudaFuncAttributeMaxDynamicSharedMemorySize, SM1);
    cudaFuncSetAttribute(hgemm<2>, cudaFuncAttributeMaxDynamicSharedMemorySize, SM2);

    // 1. weight prep (bf16 splits)
    prep_all<<<5184, 256>>>(Wq, bq, Wk, bk, Wv, bv, Wa, ba, Wdn, Wup);
    // 2. projection (fp32 f32x2) + split/sigmoid/bf16 epilogue
    gemm_proj<<<dim3(2, 64), 256>>>(x, pWcat, NTOK, 256, DMM);
    // 3. bin mma-GEMM (k @ Wd2^T, fused v-contraction -> g_bin)
    hgemm<1><<<dim3(64, 64), 256, SM1>>>(pKh, pKl, pWd2h, pWd2l, nullptr);
    // 4. A mma-GEMM (alpha @ MT^T -> g_Ah/g_Al split)   <-- ncu capture slot
    hgemm<0><<<dim3(128, 64), 256, SM0>>>(pAh, pAl, pMTh, pMTl, nullptr);
    // 5. chunk propagators (512 threads, vectorized d)
    passA_mma<<<NCH, 512, PA_SMEM>>>();
    // 6. cross-chunk scan
    passB_kern<<<BB, 512>>>();
    // 7. within-chunk recurrence
    passC_kern<<<NCH, 512>>>();
    // 8. o mma-GEMM (q @ Wu3^T, fused c-contraction -> out)
    hgemm<2><<<dim3(64, 64), 256, SM2>>>(pQh, pQl, pWu3h, pWu3l, out);
}